// round 14
// baseline (speedup 1.0000x reference)
#include <cuda_runtime.h>
#include <cuda_bf16.h>
#include <cstdint>
#include <math.h>

#define HH   8
#define DD   256
#define DKK  32
#define EE   256
#define BBB  16
#define GGG  513
#define NPP  256
#define NKEY 512

#define NORMF 0.17677669529663687f  // 1/sqrt(32)

// ---------------- scratch (static device globals; no allocation) ----------------
__device__ float g_Q[HH * BBB * GGG * DKK];
__device__ float g_K[HH * BBB * GGG * DKK];
__device__ float g_V[HH * BBB * GGG * DKK];
// g_Qx[0]=Q1(pick diag) [1]=Q2(pick->allpick) [2]=Q3(pick->alldelivery)
// g_Qx[3]=Q4(del diag)  [4]=Q5(del->alldelivery) [5]=Q6(del->allpick)
__device__ float g_Qx[6][HH * BBB * NPP * DKK];

// heads as bf16 hi/lo, [b][n][h*32+dk]
__device__ __nv_bfloat16 g_headshi[BBB * GGG * HH * DKK];
__device__ __nv_bfloat16 g_headslo[BBB * GGG * HH * DKK];

// bf16 hi/lo splits of inputs and (transposed) weights
#define XELEMS (BBB * GGG * DD)          // 2101248
__device__ __nv_bfloat16 g_qhi[XELEMS];
__device__ __nv_bfloat16 g_qlo[XELEMS];
__device__ __nv_bfloat16 g_hhi[XELEMS];
__device__ __nv_bfloat16 g_hlo[XELEMS];
// W^T: [job][head][k_out=32][d=256]
#define WTELEMS (9 * HH * DKK * DD)      // 589824
__device__ __nv_bfloat16 g_Wthi[WTELEMS];
__device__ __nv_bfloat16 g_Wtlo[WTELEMS];
// Wout^T: [e=256][f=256]
__device__ __nv_bfloat16 g_WoThi[EE * HH * DKK];
__device__ __nv_bfloat16 g_WoTlo[EE * HH * DKK];

// bf16 K (keys 1..512) and transposed V for attention MMA
__device__ __nv_bfloat16 g_Kbh[HH * BBB * NKEY * DKK];
__device__ __nv_bfloat16 g_Kbl[HH * BBB * NKEY * DKK];
__device__ __nv_bfloat16 g_Vtbh[HH * BBB * DKK * NKEY];
__device__ __nv_bfloat16 g_Vtbl[HH * BBB * DKK * NKEY];

__device__ __forceinline__ float* dst_of(int i) {
    switch (i) {
        case 0:  return g_Q;
        case 1:  return g_K;
        case 2:  return g_V;
        default: return g_Qx[i - 3];
    }
}

__device__ __forceinline__ uint32_t smem_u32(const void* p) {
    uint32_t a;
    asm("{ .reg .u64 t; cvta.to.shared.u64 t, %1; cvt.u32.u64 %0, t; }" : "=r"(a) : "l"(p));
    return a;
}

#define LDMX4(r, addr) \
    asm volatile("ldmatrix.sync.aligned.m8n8.x4.shared.b16 {%0,%1,%2,%3}, [%4];" \
        : "=r"((r)[0]), "=r"((r)[1]), "=r"((r)[2]), "=r"((r)[3]) : "r"(addr))
#define LDMX2(r, addr) \
    asm volatile("ldmatrix.sync.aligned.m8n8.x2.shared.b16 {%0,%1}, [%2];" \
        : "=r"((r)[0]), "=r"((r)[1]) : "r"(addr))

#define MMA16816(c, a, b0, b1) \
    asm volatile("mma.sync.aligned.m16n8k16.row.col.f32.bf16.bf16.f32 " \
        "{%0,%1,%2,%3}, {%4,%5,%6,%7}, {%8,%9}, {%0,%1,%2,%3};" \
        : "+f"((c)[0]), "+f"((c)[1]), "+f"((c)[2]), "+f"((c)[3]) \
        : "r"((a)[0]), "r"((a)[1]), "r"((a)[2]), "r"((a)[3]), "r"(b0), "r"(b1))

#define CP_ASYNC16(dst, src) \
    asm volatile("cp.async.cg.shared.global [%0], [%1], 16;" :: "r"(dst), "l"(src))
#define CP_COMMIT() asm volatile("cp.async.commit_group;" ::: "memory")
#define CP_WAIT0()  asm volatile("cp.async.wait_group 0;" ::: "memory")

__device__ __forceinline__ void split2(float a, float b, uint32_t& hi, uint32_t& lo) {
    __nv_bfloat16 ha = __float2bfloat16(a), hb = __float2bfloat16(b);
    __nv_bfloat162 hh = __halves2bfloat162(ha, hb);
    __nv_bfloat162 ll = __halves2bfloat162(__float2bfloat16(a - __bfloat162float(ha)),
                                           __float2bfloat16(b - __bfloat162float(hb)));
    hi = *(uint32_t*)&hh;
    lo = *(uint32_t*)&ll;
}

// =====================================================================
// Prep 1: fp32 -> bf16 hi/lo split of q and h.
// =====================================================================
__global__ __launch_bounds__(256) void cvt_x_kernel(const float* __restrict__ q,
                                                    const float* __restrict__ h) {
    const int which = blockIdx.y;
    const float* src = which ? h : q;
    __nv_bfloat16* dhi = which ? g_hhi : g_qhi;
    __nv_bfloat16* dlo = which ? g_hlo : g_qlo;

    int t = blockIdx.x * 256 + threadIdx.x;
    if (t * 8 >= XELEMS) return;
    const float4 v0 = ((const float4*)src)[t * 2];
    const float4 v1 = ((const float4*)src)[t * 2 + 1];
    float xs[8] = {v0.x, v0.y, v0.z, v0.w, v1.x, v1.y, v1.z, v1.w};
    __nv_bfloat162 hp[4], lp[4];
#pragma unroll
    for (int i = 0; i < 4; i++) {
        __nv_bfloat16 h0 = __float2bfloat16(xs[2 * i]);
        __nv_bfloat16 h1 = __float2bfloat16(xs[2 * i + 1]);
        __nv_bfloat16 l0 = __float2bfloat16(xs[2 * i] - __bfloat162float(h0));
        __nv_bfloat16 l1 = __float2bfloat16(xs[2 * i + 1] - __bfloat162float(h1));
        hp[i] = __halves2bfloat162(h0, h1);
        lp[i] = __halves2bfloat162(l0, l1);
    }
    ((uint4*)dhi)[t] = *(uint4*)hp;
    ((uint4*)dlo)[t] = *(uint4*)lp;
}

// =====================================================================
// Prep 2: W[j][h][d][k] fp32 -> W^T hi/lo bf16 [j][h][k][d]
// =====================================================================
struct WPtrs { const float* w[9]; };

__global__ __launch_bounds__(256) void cvt_w_kernel(WPtrs P) {
    int idx = blockIdx.x * 256 + threadIdx.x;
    if (idx >= WTELEMS) return;
    int j = idx >> 16;
    int h = (idx >> 13) & 7;
    int k = (idx >> 8) & 31;
    int d = idx & 255;
    float x = P.w[j][(size_t)h * DD * DKK + (size_t)d * DKK + k];
    __nv_bfloat16 hi = __float2bfloat16(x);
    __nv_bfloat16 lo = __float2bfloat16(x - __bfloat162float(hi));
    g_Wthi[idx] = hi;
    g_Wtlo[idx] = lo;
}

// Wout[f][e] fp32 -> WoutT hi/lo [e][f]
__global__ __launch_bounds__(256) void cvt_wout_kernel(const float* __restrict__ Wout) {
    int idx = blockIdx.x * 256 + threadIdx.x;   // 65536
    int e = idx >> 8, f = idx & 255;
    float x = Wout[(size_t)f * EE + e];
    __nv_bfloat16 hi = __float2bfloat16(x);
    g_WoThi[idx] = hi;
    g_WoTlo[idx] = __float2bfloat16(x - __bfloat162float(hi));
}

// =====================================================================
// Kernel A (HMMA) v4: 128 rows x 128 cols (4 heads) per block,
// cp.async 2-stage ring over 8 chunks of dc=32. (256,2).
// =====================================================================
#define PST2 40
#define PRJ_XHI 0
#define PRJ_XLO 10240
#define PRJ_WHI 20480
#define PRJ_WLO 30720
#define PRJ_STAGE 40960
#define PROJ_SMEM (2 * PRJ_STAGE)   // 81920 B

__global__ __launch_bounds__(256, 2) void proj_hmma_kernel() {
    extern __shared__ char psm[];
    const int job  = blockIdx.z;
    const int hg   = blockIdx.y;
    const int tile = blockIdx.x;

    const int off = (job < 3) ? 0 : ((job < 6) ? 1 : (NPP + 1));
    const int cnt = (job < 3) ? GGG : NPP;
    const int rows_total = BBB * cnt;
    const int row0 = tile * 128;
    if (row0 >= rows_total) return;

    const __nv_bfloat16* Xhi = (job == 0) ? g_qhi : g_hhi;
    const __nv_bfloat16* Xlo = (job == 0) ? g_qlo : g_hlo;
    const __nv_bfloat16* Whi = g_Wthi + ((size_t)(job * HH + hg * 4)) * (DKK * DD);
    const __nv_bfloat16* Wlo = g_Wtlo + ((size_t)(job * HH + hg * 4)) * (DKK * DD);
    float* dstbase = dst_of(job);

    const uint32_t sbase = smem_u32(psm);
    const int tid  = threadIdx.x;
    const int warp = tid >> 5;
    const int lane = tid & 31;
    const int g    = lane >> 2;
    const int tig  = lane & 3;
    const int wm   = warp >> 1;
    const int wn   = warp & 1;

    // ---- precompute per-thread cp.async mapping (loop-invariant but +dc) ----
    const __nv_bfloat16* srcs[8];
    uint32_t dsts[8];
#pragma unroll
    for (int i = 0; i < 8; i++) {
        int c   = tid + i * 256;          // 0..2047
        int sel = c >> 9;                 // 0=Xhi 1=Xlo 2=Whi 3=Wlo
        int cc  = c & 511;
        int row = cc >> 2;                // 0..127
        int qd  = cc & 3;                 // 8 bf16 = 16B each
        if (sel < 2) {
            int gr  = row0 + row;
            int grc = (gr < rows_total) ? gr : (rows_total - 1);
            int b    = grc / cnt;
            int nloc = grc - b * cnt;
            srcs[i] = (sel ? Xlo : Xhi) + ((size_t)(b * GGG + off + nloc)) * DD + qd * 8;
            dsts[i] = (sel ? PRJ_XLO : PRJ_XHI) + (uint32_t)row * (PST2 * 2) + qd * 16;
        } else {
            srcs[i] = ((sel == 2) ? Whi : Wlo) + (size_t)row * DD + qd * 8;
            dsts[i] = ((sel == 2) ? PRJ_WHI : PRJ_WLO) + (uint32_t)row * (PST2 * 2) + qd * 16;
        }
    }

    float acc[2][8][4];
#pragma unroll
    for (int mi = 0; mi < 2; mi++)
#pragma unroll
        for (int nf = 0; nf < 8; nf++)
#pragma unroll
            for (int i = 0; i < 4; i++) acc[mi][nf][i] = 0.f;

    // ldmatrix offsets within a stage
    const int rowA  = wm * 32 + (lane & 7) + ((lane >> 3) & 1) * 8;
    const int colA0 = ((lane >> 4) & 1) * 8;
    const uint32_t aOff = (uint32_t)(rowA * PST2 + colA0) * 2;
    const int rowB  = lane & 7;
    const int colB0 = ((lane >> 3) & 1) * 8;
    const int nfsel = (lane >> 4) & 1;
    uint32_t bOffP[4];
#pragma unroll
    for (int p = 0; p < 4; p++) {
        int wrow = wn * 64 + p * 16 + nfsel * 8 + rowB;
        bOffP[p] = (uint32_t)(wrow * PST2 + colB0) * 2;
    }

    // prefetch chunk 0
#pragma unroll
    for (int i = 0; i < 8; i++) CP_ASYNC16(sbase + dsts[i], srcs[i]);
    CP_COMMIT();

#pragma unroll 1
    for (int c = 0; c < 8; c++) {
        CP_WAIT0();
        __syncthreads();
        if (c < 7) {
            const uint32_t stN = sbase + ((c + 1) & 1) * PRJ_STAGE;
            const int dcN = (c + 1) * 32;
#pragma unroll
            for (int i = 0; i < 8; i++) CP_ASYNC16(stN + dsts[i], srcs[i] + dcN);
            CP_COMMIT();
        }

        const uint32_t st = sbase + (c & 1) * PRJ_STAGE;
#pragma unroll
        for (int ks = 0; ks < 2; ks++) {
            const uint32_t kadd = ks * 32;
            uint32_t ahi[2][4], alo[2][4];
#pragma unroll
            for (int mi = 0; mi < 2; mi++) {
                LDMX4(ahi[mi], st + PRJ_XHI + aOff + mi * (16 * PST2 * 2) + kadd);
                LDMX4(alo[mi], st + PRJ_XLO + aOff + mi * (16 * PST2 * 2) + kadd);
            }
#pragma unroll
            for (int p = 0; p < 4; p++) {
                uint32_t bh[4], bl[4];
                LDMX4(bh, st + PRJ_WHI + bOffP[p] + kadd);
                LDMX4(bl, st + PRJ_WLO + bOffP[p] + kadd);
#pragma unroll
                for (int mi = 0; mi < 2; mi++) {
                    MMA16816(acc[mi][2 * p],     ahi[mi], bh[0], bh[1]);
                    MMA16816(acc[mi][2 * p],     alo[mi], bh[0], bh[1]);
                    MMA16816(acc[mi][2 * p],     ahi[mi], bl[0], bl[1]);
                    MMA16816(acc[mi][2 * p + 1], ahi[mi], bh[2], bh[3]);
                    MMA16816(acc[mi][2 * p + 1], alo[mi], bh[2], bh[3]);
                    MMA16816(acc[mi][2 * p + 1], ahi[mi], bl[2], bl[3]);
                }
            }
        }
    }

#pragma unroll
    for (int mi = 0; mi < 2; mi++) {
        const int r0 = row0 + wm * 32 + mi * 16 + g;
        const int r1 = r0 + 8;
#pragma unroll
        for (int nf = 0; nf < 8; nf++) {
            const int bc = wn * 64 + nf * 8 + tig * 2;
            const int hl = bc >> 5;
            const int cc = bc & 31;
            float* dst = dstbase + (size_t)(hg * 4 + hl) * rows_total * DKK;
            if (r0 < rows_total) {
                float2 v = make_float2(acc[mi][nf][0], acc[mi][nf][1]);
                *(float2*)(dst + (size_t)r0 * DKK + cc) = v;
            }
            if (r1 < rows_total) {
                float2 v = make_float2(acc[mi][nf][2], acc[mi][nf][3]);
                *(float2*)(dst + (size_t)r1 * DKK + cc) = v;
            }
        }
    }
}

// =====================================================================
// Prep 3: K,V fp32 -> bf16 hi/lo; V transposed per hb.
// =====================================================================
__global__ __launch_bounds__(256) void cvt_kv_kernel() {
    const int kt = blockIdx.x;
    const int hb = blockIdx.y;
    const int tid = threadIdx.x;
    __shared__ float vs[64][33];

#pragma unroll
    for (int i = 0; i < 8; i++) {
        int idx = tid + i * 256;
        int key = idx >> 5;
        int dk  = idx & 31;
        size_t gsrc = ((size_t)hb * GGG + 1 + kt * 64 + key) * DKK + dk;
        float kv = g_K[gsrc];
        __nv_bfloat16 kh = __float2bfloat16(kv);
        size_t kd = ((size_t)hb * NKEY + kt * 64 + key) * DKK + dk;
        g_Kbh[kd] = kh;
        g_Kbl[kd] = __float2bfloat16(kv - __bfloat162float(kh));
        vs[key][dk] = g_V[gsrc];
    }
    __syncthreads();
#pragma unroll
    for (int i = 0; i < 8; i++) {
        int idx = tid + i * 256;
        int d = idx >> 6;
        int j = idx & 63;
        float vv = vs[j][d];
        __nv_bfloat16 vh = __float2bfloat16(vv);
        size_t o = ((size_t)hb * DKK + d) * NKEY + kt * 64 + j;
        g_Vtbh[o] = vh;
        g_Vtbl[o] = __float2bfloat16(vv - __bfloat162float(vh));
    }
}

// =====================================================================
// Kernel B (HMMA flash attention) — half-tile softmax + cp.async
// 2-stage K/V double buffer. __launch_bounds__(256,2). (proven R13)
// =====================================================================
#define STQ 40
#define STK 40
#define STV 72
#define O_QMHI 0
#define O_QMLO 10240
#define O_EPHI 20480
#define O_EPLO 30720
#define O_EDHI 40960
#define O_EDLO 51200
#define O_KV   61440
#define KV_STAGE 19456
#define KV_KHI 0
#define KV_KLO 5120
#define KV_VHI 10240
#define KV_VLO 14848
#define SMEM_ATTN (O_KV + 2 * KV_STAGE)   // 100352

__device__ __forceinline__ void load_kv_tile(uint32_t sbase, int stage, int hb, int t, int tid) {
    const uint32_t dstS = sbase + O_KV + stage * KV_STAGE;
#pragma unroll
    for (int i = 0; i < 4; i++) {
        int c = tid + i * 256;            // 0..1023
        if (c < 512) {
            int half = c >> 8;            // 0 hi, 1 lo
            int cc = c & 255;
            int row = cc >> 2, qd = cc & 3;
            const __nv_bfloat16* src = (half ? g_Kbl : g_Kbh)
                + ((size_t)hb * NKEY + t * 64 + row) * DKK + qd * 8;
            uint32_t dst = dstS + (half ? KV_KLO : KV_KHI) + row * (STK * 2) + qd * 16;
            CP_ASYNC16(dst, src);
        } else {
            int half = (c >> 8) & 1;
            int cc = c & 255;
            int row = cc >> 3, qd = cc & 7;
            const __nv_bfloat16* src = (half ? g_Vtbl : g_Vtbh)
                + ((size_t)hb * DKK + row) * NKEY + t * 64 + qd * 8;
            uint32_t dst = dstS + (half ? KV_VLO : KV_VHI) + row * (STV * 2) + qd * 16;
            CP_ASYNC16(dst, src);
        }
    }
}

__global__ __launch_bounds__(256, 2) void attn_hmma_kernel() {
    extern __shared__ char sm[];
    const int qbase = blockIdx.x * 128;
    const int b     = blockIdx.y;
    const int head  = blockIdx.z;
    const int hb    = head * BBB + b;
    const int tid   = threadIdx.x;
    const int warp  = tid >> 5;
    const int lane  = tid & 31;
    const int g     = lane >> 2;
    const int tig   = lane & 3;

    const uint32_t sbase = smem_u32(sm);
    __nv_bfloat16* sQmHi = (__nv_bfloat16*)(sm + O_QMHI);
    __nv_bfloat16* sQmLo = (__nv_bfloat16*)(sm + O_QMLO);
    __nv_bfloat16* sEpHi = (__nv_bfloat16*)(sm + O_EPHI);
    __nv_bfloat16* sEpLo = (__nv_bfloat16*)(sm + O_EPLO);
    __nv_bfloat16* sEdHi = (__nv_bfloat16*)(sm + O_EDHI);
    __nv_bfloat16* sEdLo = (__nv_bfloat16*)(sm + O_EDLO);

    // issue tile 0 loads before the prologue so they overlap it
    load_kv_tile(sbase, 0, hb, 0, tid);
    CP_COMMIT();

    // ---- prologue: convert queries into smem (scaled, hi/lo) ----
    for (int idx = tid; idx < 1024; idx += 256) {
        int row = idx >> 3, c4 = idx & 7;
        int qq = qbase + row;
        int qc = (qq < GGG) ? qq : (GGG - 1);
        const int so = row * STQ + c4 * 4;
        {
            const float4 v = *(const float4*)(g_Q + ((size_t)hb * GGG + qc) * DKK + c4 * 4);
            uint32_t h0, l0, h1, l1;
            split2(v.x * NORMF, v.y * NORMF, h0, l0);
            split2(v.z * NORMF, v.w * NORMF, h1, l1);
            *(uint2*)(sQmHi + so) = make_uint2(h0, h1);
            *(uint2*)(sQmLo + so) = make_uint2(l0, l1);
        }
        if (qc == 0) {
            *(uint2*)(sEpHi + so) = make_uint2(0, 0);
            *(uint2*)(sEpLo + so) = make_uint2(0, 0);
            *(uint2*)(sEdHi + so) = make_uint2(0, 0);
            *(uint2*)(sEdLo + so) = make_uint2(0, 0);
        } else {
            bool pick = (qc <= NPP);
            int ppd = pick ? (qc - 1) : (qc - NPP - 1);
            size_t xo = ((size_t)hb * NPP + ppd) * DKK + c4 * 4;
            const float4 ve = *(const float4*)((pick ? g_Qx[1] : g_Qx[5]) + xo);
            const float4 vd = *(const float4*)((pick ? g_Qx[2] : g_Qx[4]) + xo);
            uint32_t h0, l0, h1, l1;
            split2(ve.x * NORMF, ve.y * NORMF, h0, l0);
            split2(ve.z * NORMF, ve.w * NORMF, h1, l1);
            *(uint2*)(sEpHi + so) = make_uint2(h0, h1);
            *(uint2*)(sEpLo + so) = make_uint2(l0, l1);
            split2(vd.x * NORMF, vd.y * NORMF, h0, l0);
            split2(vd.z * NORMF, vd.w * NORMF, h1, l1);
            *(uint2*)(sEdHi + so) = make_uint2(h0, h1);
            *(uint2*)(sEdLo + so) = make_uint2(l0, l1);
        }
    }

    // ---- init from key 0 (main query only) ----
    const int r0g = qbase + warp * 16 + g;
    const int r1g = r0g + 8;
    float m0, m1, l0, l1;
    float acc[4][4];
    {
        const float* K0 = g_K + (size_t)hb * GGG * DKK;
        const float* V0 = g_V + (size_t)hb * GGG * DKK;
        int rc0 = (r0g < GGG) ? r0g : (GGG - 1);
        int rc1 = (r1g < GGG) ? r1g : (GGG - 1);
        const float* q0 = g_Q + ((size_t)hb * GGG + rc0) * DKK;
        const float* q1 = g_Q + ((size_t)hb * GGG + rc1) * DKK;
        float s0 = 0.f, s1 = 0.f;
#pragma unroll
        for (int k = 0; k < DKK; k++) {
            float kk = K0[k];
            s0 = fmaf(q0[k], kk, s0);
            s1 = fmaf(q1[k], kk, s1);
        }
        m0 = s0 * NORMF;
        m1 = s1 * NORMF;
        l0 = (tig == 0) ? 1.f : 0.f;
        l1 = l0;
#pragma unroll
        for (int vf = 0; vf < 4; vf++) {
            float va = V0[vf * 8 + 2 * tig];
            float vb = V0[vf * 8 + 2 * tig + 1];
            acc[vf][0] = va; acc[vf][1] = vb;
            acc[vf][2] = va; acc[vf][3] = vb;
        }
    }

    // ldmatrix addresses
    const int rowA  = warp * 16 + (lane & 7) + ((lane >> 3) & 1) * 8;
    const int colA0 = ((lane >> 4) & 1) * 8;
    const uint32_t aoff = (uint32_t)(rowA * STQ + colA0) * 2;
    const uint32_t aQmHi = sbase + O_QMHI + aoff;
    const uint32_t aQmLo = sbase + O_QMLO + aoff;
    const uint32_t aEpHi = sbase + O_EPHI + aoff;
    const uint32_t aEpLo = sbase + O_EPLO + aoff;
    const uint32_t aEdHi = sbase + O_EDHI + aoff;
    const uint32_t aEdLo = sbase + O_EDLO + aoff;
    const int rowB  = lane & 7;
    const int colB0 = ((lane >> 3) & 1) * 8;
    const uint32_t bKoff = (uint32_t)(rowB * STK + colB0) * 2;
    const uint32_t bVoff = (uint32_t)(rowB * STV + colB0) * 2;

    const bool extra0 = (r0g != 0);

#pragma unroll 1
    for (int t = 0; t < 8; t++) {
        CP_WAIT0();
        __syncthreads();
        if (t < 7) {
            load_kv_tile(sbase, (t + 1) & 1, hb, t + 1, tid);
            CP_COMMIT();
        }

        const uint32_t stK = sbase + O_KV + (t & 1) * KV_STAGE;
        const uint32_t aEHi = (t < 4) ? aEpHi : aEdHi;
        const uint32_t aELo = (t < 4) ? aEpLo : aEdLo;

#pragma unroll
        for (int half = 0; half < 2; half++) {
            float S1[4][4], S2[4][4];
#pragma unroll
            for (int nf = 0; nf < 4; nf++)
#pragma unroll
                for (int j = 0; j < 4; j++) { S1[nf][j] = 0.f; S2[nf][j] = 0.f; }

#pragma unroll
            for (int ks = 0; ks < 2; ks++) {
                uint32_t am[4], al[4], ae[4], af[4];
                LDMX4(am, aQmHi + ks * 32);
                LDMX4(al, aQmLo + ks * 32);
                LDMX4(ae, aEHi + ks * 32);
                LDMX4(af, aELo + ks * 32);
#pragma unroll
                for (int nf = 0; nf < 4; nf++) {
                    uint32_t kaddr = stK + bKoff + (uint32_t)((half * 4 + nf) * 8) * (STK * 2) + ks * 32;
                    uint32_t kh[2], kl[2];
                    LDMX2(kh, kaddr + KV_KHI);
                    LDMX2(kl, kaddr + KV_KLO);
                    MMA16816(S1[nf], am, kh[0], kh[1]);
                    MMA16816(S1[nf], al, kh[0], kh[1]);
                    MMA16816(S1[nf], am, kl[0], kl[1]);
                    MMA16816(S2[nf], ae, kh[0], kh[1]);
                    MMA16816(S2[nf], af, kh[0], kh[1]);
                    MMA16816(S2[nf], ae, kl[0], kl[1]);
                }
            }

            float mx0 = -3.0e38f, mx1 = -3.0e38f;
#pragma unroll
            for (int nf = 0; nf < 4; nf++) {
                mx0 = fmaxf(mx0, fmaxf(S1[nf][0], S1[nf][1]));
                mx1 = fmaxf(mx1, fmaxf(S1[nf][2], S1[nf][3]));
                if (extra0) mx0 = fmaxf(mx0, fmaxf(S2[nf][0], S2[nf][1]));
                mx1 = fmaxf(mx1, fmaxf(S2[nf][2], S2[nf][3]));
            }
            mx0 = fmaxf(mx0, __shfl_xor_sync(0xffffffffu, mx0, 1));
            mx0 = fmaxf(mx0, __shfl_xor_sync(0xffffffffu, mx0, 2));
            mx1 = fmaxf(mx1, __shfl_xor_sync(0xffffffffu, mx1, 1));
            mx1 = fmaxf(mx1, __shfl_xor_sync(0xffffffffu, mx1, 2));

            float mn0 = fmaxf(m0, mx0), mn1 = fmaxf(m1, mx1);
            float c0 = __expf(m0 - mn0), c1 = __expf(m1 - mn1);
            m0 = mn0; m1 = mn1;
            l0 *= c0; l1 *= c1;
#pragma unroll
            for (int vf = 0; vf < 4; vf++) {
                acc[vf][0] *= c0; acc[vf][1] *= c0;
                acc[vf][2] *= c1; acc[vf][3] *= c1;
            }
#pragma unroll
            for (int nf = 0; nf < 4; nf++) {
                float w0 = __expf(S1[nf][0] - m0);
                float w1 = __expf(S1[nf][1] - m0);
                float w2 = __expf(S1[nf][2] - m1);
                float w3 = __expf(S1[nf][3] - m1);
                if (extra0) {
                    w0 += __expf(S2[nf][0] - m0);
                    w1 += __expf(S2[nf][1] - m0);
                }
                w2 += __expf(S2[nf][2] - m1);
                w3 += __expf(S2[nf][3] - m1);
                l0 += w0 + w1; l1 += w2 + w3;
                S1[nf][0] = w0; S1[nf][1] = w1; S1[nf][2] = w2; S1[nf][3] = w3;
            }

#pragma unroll
            for (int ks2 = 0; ks2 < 2; ks2++) {
                uint32_t ph[4], pl[4];
                split2(S1[2 * ks2][0], S1[2 * ks2][1], ph[0], pl[0]);
                split2(S1[2 * ks2][2], S1[2 * ks2][3], ph[1], pl[1]);
                split2(S1[2 * ks2 + 1][0], S1[2 * ks2 + 1][1], ph[2], pl[2]);
                split2(S1[2 * ks2 + 1][2], S1[2 * ks2 + 1][3], ph[3], pl[3]);
#pragma unroll
                for (int vf = 0; vf < 4; vf++) {
                    uint32_t vaddr = stK + bVoff + (uint32_t)(vf * 8) * (STV * 2)
                                   + (half * 2 + ks2) * 32;
                    uint32_t vh[2], vl[2];
                    LDMX2(vh, vaddr + KV_VHI);
                    LDMX2(vl, vaddr + KV_VLO);
                    MMA16816(acc[vf], ph, vh[0], vh[1]);
                    MMA16816(acc[vf], pl, vh[0], vh[1]);
                    MMA16816(acc[vf], ph, vl[0], vl[1]);
                }
            }
        }
    }

    // ---- diagonal extra logit (single key per row) ----
#pragma unroll
    for (int r = 0; r < 2; r++) {
        int qq = (r == 0) ? r0g : r1g;
        if (qq >= 1 && qq < GGG) {
            bool pick = (qq <= NPP);
            int nd = pick ? (NPP + qq) : (qq - NPP);
            int ppd = pick ? (qq - 1) : (qq - NPP - 1);
            const float* qg = (pick ? g_Qx[0] : g_Qx[3]) + ((size_t)hb * NPP + ppd) * DKK;
            const float* kk = g_K + ((size_t)hb * GGG + nd) * DKK;
            const float* vv = g_V + ((size_t)hb * GGG + nd) * DKK;
            float s = 0.f;
#pragma unroll
            for (int k = 0; k < DKK; k++) s = fmaf(qg[k], kk[k], s);
            s *= NORMF;
            float& m = (r == 0) ? m0 : m1;
            float& l = (r == 0) ? l0 : l1;
            float mn = fmaxf(m, s);
            float c = __expf(m - mn);
            m = mn;
            l *= c;
#pragma unroll
            for (int vf = 0; vf < 4; vf++) {
                acc[vf][2 * r] *= c;
                acc[vf][2 * r + 1] *= c;
            }
            float w = __expf(s - mn);
            if (tig == 0) l += w;
#pragma unroll
            for (int vf = 0; vf < 4; vf++) {
                acc[vf][2 * r]     = fmaf(w, vv[vf * 8 + 2 * tig], acc[vf][2 * r]);
                acc[vf][2 * r + 1] = fmaf(w, vv[vf * 8 + 2 * tig + 1], acc[vf][2 * r + 1]);
            }
        }
    }

    // ---- finalize: write heads as bf16 hi/lo ----
    l0 += __shfl_xor_sync(0xffffffffu, l0, 1);
    l0 += __shfl_xor_sync(0xffffffffu, l0, 2);
    l1 += __shfl_xor_sync(0xffffffffu, l1, 1);
    l1 += __shfl_xor_sync(0xffffffffu, l1, 2);
    float inv0 = 1.f / l0, inv1 = 1.f / l1;

    if (r0g < GGG) {
        size_t base = ((size_t)(b * GGG + r0g) * HH + head) * DKK;
#pragma unroll
        for (int vf = 0; vf < 4; vf++) {
            uint32_t hi, lo;
            split2(acc[vf][0] * inv0, acc[vf][1] * inv0, hi, lo);
            *(uint32_t*)(g_headshi + base + vf * 8 + 2 * tig) = hi;
            *(uint32_t*)(g_headslo + base + vf * 8 + 2 * tig) = lo;
        }
    }
    if (r1g < GGG) {
        size_t base = ((size_t)(b * GGG + r1g) * HH + head) * DKK;
#pragma unroll
        for (int vf = 0; vf < 4; vf++) {
            uint32_t hi, lo;
            split2(acc[vf][2] * inv1, acc[vf][3] * inv1, hi, lo);
            *(uint32_t*)(g_headshi + base + vf * 8 + 2 * tig) = hi;
            *(uint32_t*)(g_headslo + base + vf * 8 + 2 * tig) = lo;
        }
    }
}

// =====================================================================
// Kernel C (HMMA): out = heads(8208x256) @ WoutT^T.  Paired-B x4 loads.
// =====================================================================
#define XS_STRIDE 72

__global__ __launch_bounds__(256) void out_hmma_kernel(float* __restrict__ out) {
    const int M = BBB * GGG;
    const int row0 = blockIdx.x * 128;
    const int col0 = blockIdx.y * 32;
    if (row0 >= M) return;

    __shared__ __nv_bfloat16 Xs[2][128][XS_STRIDE];
    __shared__ __nv_bfloat16 Ws[2][32][XS_STRIDE];

    const int tid  = threadIdx.x;
    const int warp = tid >> 5;
    const int lane = tid & 31;
    const int g    = lane >> 2;
    const int tig  = lane & 3;

    float acc[4][4];
#pragma unroll
    for (int nf = 0; nf < 4; nf++)
#pragma unroll
        for (int i = 0; i < 4; i++) acc[nf][i] = 0.f;

    const int rowA  = warp * 16 + (lane & 7) + ((lane >> 3) & 1) * 8;
    const int colA0 = ((lane >> 4) & 1) * 8;
    const uint32_t addrAhi0 = smem_u32(&Xs[0][rowA][colA0]);
    const uint32_t addrAlo0 = smem_u32(&Xs[1][rowA][colA0]);
    const int rowB  = lane & 7;
    const int colB0 = ((lane >> 3) & 1) * 8;
    const int nfsel = (lane >> 4) & 1;
    uint32_t addrBhiP[2], addrBloP[2];
#pragma unroll
    for (int p = 0; p < 2; p++) {
        addrBhiP[p] = smem_u32(&Ws[0][(2 * p + nfsel) * 8 + rowB][colB0]);
        addrBloP[p] = smem_u32(&Ws[1][(2 * p + nfsel) * 8 + rowB][colB0]);
    }

#pragma unroll 1
    for (int c = 0; c < 4; c++) {
        const int dc = c * 64;
        __syncthreads();
#pragma unroll
        for (int i = 0; i < 4; i++) {
            int idx = tid + i * 256;
            int row = idx >> 3;
            int v   = idx & 7;
            int gr  = row0 + row;
            int grc = (gr < M) ? gr : (M - 1);
            size_t gix = (size_t)grc * 256 + dc + v * 8;
            *(uint4*)&Xs[0][row][v * 8] = *(const uint4*)(g_headshi + gix);
            *(uint4*)&Xs[1][row][v * 8] = *(const uint4*)(g_headslo + gix);
        }
        {
            int row = tid >> 3;
            int v   = tid & 7;
            size_t gix = (size_t)(col0 + row) * 256 + dc + v * 8;
            *(uint4*)&Ws[0][row][v * 8] = *(const uint4*)(g_WoThi + gix);
            *(uint4*)&Ws[1][row][v * 8] = *(const uint4*)(g_WoTlo + gix);
        }
        __syncthreads();

#pragma unroll
        for (int ks = 0; ks < 4; ks++) {
            const uint32_t kadd = ks * 32;
            uint32_t ahi[4], alo[4];
            LDMX4(ahi, addrAhi0 + kadd);
            LDMX4(alo, addrAlo0 + kadd);
#pragma unroll
            for (int p = 0; p < 2; p++) {
                uint32_t bh[4], bl[4];
                LDMX4(bh, addrBhiP[p] + kadd);
                LDMX4(bl, addrBloP[p] + kadd);
                MMA16816(acc[2 * p],     ahi, bh[0], bh[1]);
                MMA16816(acc[2 * p],     alo, bh[0], bh[1]);
                MMA16816(acc[2 * p],     ahi, bl[0], bl[1]);
                MMA16816(acc[2 * p + 1], ahi, bh[2], bh[3]);
                MMA16816(acc[2 * p + 1], alo, bh[2], bh[3]);
                MMA16816(acc[2 * p + 1], ahi, bl[2], bl[3]);
            }
        }
    }

    const int r0 = row0 + warp * 16 + g;
    const int r1 = r0 + 8;
#pragma unroll
    for (int nf = 0; nf < 4; nf++) {
        const int col = col0 + nf * 8 + tig * 2;
        if (r0 < M) {
            float2 v = make_float2(acc[nf][0], acc[nf][1]);
            *(float2*)(out + (size_t)r0 * EE + col) = v;
        }
        if (r1 < M) {
            float2 v = make_float2(acc[nf][2], acc[nf][3]);
            *(float2*)(out + (size_t)r1 * EE + col) = v;
        }
    }
}

// =====================================================================
extern "C" void kernel_launch(void* const* d_in, const int* in_sizes, int n_in,
                              void* d_out, int out_size) {
    const float* q = (const float*)d_in[0];
    const float* h = (const float*)d_in[1];
    WPtrs WP;
    for (int i = 0; i < 9; i++) WP.w[i] = (const float*)d_in[2 + i];
    const float* Wout = (const float*)d_in[11];
    float* out = (float*)d_out;

    cudaFuncSetAttribute(attn_hmma_kernel, cudaFuncAttributeMaxDynamicSharedMemorySize, SMEM_ATTN);
    cudaFuncSetAttribute(proj_hmma_kernel, cudaFuncAttributeMaxDynamicSharedMemorySize, PROJ_SMEM);

    cvt_x_kernel<<<dim3((XELEMS / 8 + 255) / 256, 2), 256>>>(q, h);
    cvt_w_kernel<<<(WTELEMS + 255) / 256, 256>>>(WP);
    cvt_wout_kernel<<<(EE * HH * DKK + 255) / 256, 256>>>(Wout);

    proj_hmma_kernel<<<dim3(65, 2, 9), 256, PROJ_SMEM>>>();

    cvt_kv_kernel<<<dim3(8, HH * BBB), 256>>>();

    attn_hmma_kernel<<<dim3(5, BBB, HH), 256, SMEM_ATTN>>>();

    out_hmma_kernel<<<dim3((BBB * GGG + 127) / 128, EE / 32), 256>>>(out);
}

// round 15
// speedup vs baseline: 1.0109x; 1.0109x over previous
#include <cuda_runtime.h>
#include <cuda_bf16.h>
#include <cstdint>
#include <math.h>

#define HH   8
#define DD   256
#define DKK  32
#define EE   256
#define BBB  16
#define GGG  513
#define NPP  256
#define NKEY 512

#define NORMF 0.17677669529663687f  // 1/sqrt(32)

// ---------------- scratch (static device globals; no allocation) ----------------
__device__ float g_Q[HH * BBB * GGG * DKK];
__device__ float g_K[HH * BBB * GGG * DKK];
__device__ float g_V[HH * BBB * GGG * DKK];
// g_Qx[0]=Q1(pick diag) [1]=Q2(pick->allpick) [2]=Q3(pick->alldelivery)
// g_Qx[3]=Q4(del diag)  [4]=Q5(del->alldelivery) [5]=Q6(del->allpick)
__device__ float g_Qx[6][HH * BBB * NPP * DKK];

// heads as bf16 hi/lo, [b][n][h*32+dk]
__device__ __nv_bfloat16 g_headshi[BBB * GGG * HH * DKK];
__device__ __nv_bfloat16 g_headslo[BBB * GGG * HH * DKK];

// bf16 hi/lo splits of inputs and (transposed) weights
#define XELEMS (BBB * GGG * DD)          // 2101248
__device__ __nv_bfloat16 g_qhi[XELEMS];
__device__ __nv_bfloat16 g_qlo[XELEMS];
__device__ __nv_bfloat16 g_hhi[XELEMS];
__device__ __nv_bfloat16 g_hlo[XELEMS];
// W^T: [job][head][k_out=32][d=256]
#define WTELEMS (9 * HH * DKK * DD)      // 589824
__device__ __nv_bfloat16 g_Wthi[WTELEMS];
__device__ __nv_bfloat16 g_Wtlo[WTELEMS];
// Wout^T: [e=256][f=256]
__device__ __nv_bfloat16 g_WoThi[EE * HH * DKK];
__device__ __nv_bfloat16 g_WoTlo[EE * HH * DKK];

// bf16 K (keys 1..512) and transposed V for attention MMA
__device__ __nv_bfloat16 g_Kbh[HH * BBB * NKEY * DKK];
__device__ __nv_bfloat16 g_Kbl[HH * BBB * NKEY * DKK];
__device__ __nv_bfloat16 g_Vtbh[HH * BBB * DKK * NKEY];
__device__ __nv_bfloat16 g_Vtbl[HH * BBB * DKK * NKEY];

__device__ __forceinline__ float* dst_of(int i) {
    switch (i) {
        case 0:  return g_Q;
        case 1:  return g_K;
        case 2:  return g_V;
        default: return g_Qx[i - 3];
    }
}

__device__ __forceinline__ uint32_t smem_u32(const void* p) {
    uint32_t a;
    asm("{ .reg .u64 t; cvta.to.shared.u64 t, %1; cvt.u32.u64 %0, t; }" : "=r"(a) : "l"(p));
    return a;
}

#define LDMX4(r, addr) \
    asm volatile("ldmatrix.sync.aligned.m8n8.x4.shared.b16 {%0,%1,%2,%3}, [%4];" \
        : "=r"((r)[0]), "=r"((r)[1]), "=r"((r)[2]), "=r"((r)[3]) : "r"(addr))
#define LDMX2(r, addr) \
    asm volatile("ldmatrix.sync.aligned.m8n8.x2.shared.b16 {%0,%1}, [%2];" \
        : "=r"((r)[0]), "=r"((r)[1]) : "r"(addr))

#define MMA16816(c, a, b0, b1) \
    asm volatile("mma.sync.aligned.m16n8k16.row.col.f32.bf16.bf16.f32 " \
        "{%0,%1,%2,%3}, {%4,%5,%6,%7}, {%8,%9}, {%0,%1,%2,%3};" \
        : "+f"((c)[0]), "+f"((c)[1]), "+f"((c)[2]), "+f"((c)[3]) \
        : "r"((a)[0]), "r"((a)[1]), "r"((a)[2]), "r"((a)[3]), "r"(b0), "r"(b1))

#define CP_ASYNC16(dst, src) \
    asm volatile("cp.async.cg.shared.global [%0], [%1], 16;" :: "r"(dst), "l"(src))
#define CP_COMMIT() asm volatile("cp.async.commit_group;" ::: "memory")
#define CP_WAIT0()  asm volatile("cp.async.wait_group 0;" ::: "memory")

__device__ __forceinline__ void split2(float a, float b, uint32_t& hi, uint32_t& lo) {
    __nv_bfloat16 ha = __float2bfloat16(a), hb = __float2bfloat16(b);
    __nv_bfloat162 hh = __halves2bfloat162(ha, hb);
    __nv_bfloat162 ll = __halves2bfloat162(__float2bfloat16(a - __bfloat162float(ha)),
                                           __float2bfloat16(b - __bfloat162float(hb)));
    hi = *(uint32_t*)&hh;
    lo = *(uint32_t*)&ll;
}

// =====================================================================
// Prep 1: fp32 -> bf16 hi/lo split of q and h.
// =====================================================================
__global__ __launch_bounds__(256) void cvt_x_kernel(const float* __restrict__ q,
                                                    const float* __restrict__ h) {
    const int which = blockIdx.y;
    const float* src = which ? h : q;
    __nv_bfloat16* dhi = which ? g_hhi : g_qhi;
    __nv_bfloat16* dlo = which ? g_hlo : g_qlo;

    int t = blockIdx.x * 256 + threadIdx.x;
    if (t * 8 >= XELEMS) return;
    const float4 v0 = ((const float4*)src)[t * 2];
    const float4 v1 = ((const float4*)src)[t * 2 + 1];
    float xs[8] = {v0.x, v0.y, v0.z, v0.w, v1.x, v1.y, v1.z, v1.w};
    __nv_bfloat162 hp[4], lp[4];
#pragma unroll
    for (int i = 0; i < 4; i++) {
        __nv_bfloat16 h0 = __float2bfloat16(xs[2 * i]);
        __nv_bfloat16 h1 = __float2bfloat16(xs[2 * i + 1]);
        __nv_bfloat16 l0 = __float2bfloat16(xs[2 * i] - __bfloat162float(h0));
        __nv_bfloat16 l1 = __float2bfloat16(xs[2 * i + 1] - __bfloat162float(h1));
        hp[i] = __halves2bfloat162(h0, h1);
        lp[i] = __halves2bfloat162(l0, l1);
    }
    ((uint4*)dhi)[t] = *(uint4*)hp;
    ((uint4*)dlo)[t] = *(uint4*)lp;
}

// =====================================================================
// Prep 2: W[j][h][d][k] fp32 -> W^T hi/lo bf16 [j][h][k][d]
// =====================================================================
struct WPtrs { const float* w[9]; };

__global__ __launch_bounds__(256) void cvt_w_kernel(WPtrs P) {
    int idx = blockIdx.x * 256 + threadIdx.x;
    if (idx >= WTELEMS) return;
    int j = idx >> 16;
    int h = (idx >> 13) & 7;
    int k = (idx >> 8) & 31;
    int d = idx & 255;
    float x = P.w[j][(size_t)h * DD * DKK + (size_t)d * DKK + k];
    __nv_bfloat16 hi = __float2bfloat16(x);
    __nv_bfloat16 lo = __float2bfloat16(x - __bfloat162float(hi));
    g_Wthi[idx] = hi;
    g_Wtlo[idx] = lo;
}

// Wout[f][e] fp32 -> WoutT hi/lo [e][f]
__global__ __launch_bounds__(256) void cvt_wout_kernel(const float* __restrict__ Wout) {
    int idx = blockIdx.x * 256 + threadIdx.x;   // 65536
    int e = idx >> 8, f = idx & 255;
    float x = Wout[(size_t)f * EE + e];
    __nv_bfloat16 hi = __float2bfloat16(x);
    g_WoThi[idx] = hi;
    g_WoTlo[idx] = __float2bfloat16(x - __bfloat162float(hi));
}

// =====================================================================
// Kernel A (HMMA) v3 (R13-proven): 128 rows x 128 cols (4 heads)/block,
// dc=64 sync fills. __launch_bounds__(256,2).
// =====================================================================
#define PST 72
#define PROJ_SMEM (4 * 128 * PST * 2)   // 73728 B

__global__ __launch_bounds__(256, 2) void proj_hmma_kernel() {
    extern __shared__ __nv_bfloat16 dsm[];
    const int job  = blockIdx.z;
    const int hg   = blockIdx.y;
    const int tile = blockIdx.x;

    const int off = (job < 3) ? 0 : ((job < 6) ? 1 : (NPP + 1));
    const int cnt = (job < 3) ? GGG : NPP;
    const int rows_total = BBB * cnt;
    const int row0 = tile * 128;
    if (row0 >= rows_total) return;

    const __nv_bfloat16* Xhi = (job == 0) ? g_qhi : g_hhi;
    const __nv_bfloat16* Xlo = (job == 0) ? g_qlo : g_hlo;
    const __nv_bfloat16* Whi = g_Wthi + ((size_t)(job * HH + hg * 4)) * (DKK * DD);
    const __nv_bfloat16* Wlo = g_Wtlo + ((size_t)(job * HH + hg * 4)) * (DKK * DD);
    float* dstbase = dst_of(job);

    __nv_bfloat16* Xs0 = dsm;
    __nv_bfloat16* Xs1 = dsm + 128 * PST;
    __nv_bfloat16* Ws0 = dsm + 2 * 128 * PST;
    __nv_bfloat16* Ws1 = dsm + 3 * 128 * PST;

    const int tid  = threadIdx.x;
    const int warp = tid >> 5;
    const int lane = tid & 31;
    const int g    = lane >> 2;
    const int tig  = lane & 3;
    const int wm   = warp >> 1;
    const int wn   = warp & 1;

    float acc[2][8][4];
#pragma unroll
    for (int mi = 0; mi < 2; mi++)
#pragma unroll
        for (int nf = 0; nf < 8; nf++)
#pragma unroll
            for (int i = 0; i < 4; i++) acc[mi][nf][i] = 0.f;

    const int rowA  = wm * 32 + (lane & 7) + ((lane >> 3) & 1) * 8;
    const int colA0 = ((lane >> 4) & 1) * 8;
    const uint32_t aHi0 = smem_u32(&Xs0[rowA * PST + colA0]);
    const uint32_t aLo0 = smem_u32(&Xs1[rowA * PST + colA0]);
    const int rowB  = lane & 7;
    const int colB0 = ((lane >> 3) & 1) * 8;
    const int nfsel = (lane >> 4) & 1;
    uint32_t bHiP[4], bLoP[4];
#pragma unroll
    for (int p = 0; p < 4; p++) {
        int wrow = wn * 64 + p * 16 + nfsel * 8 + rowB;
        bHiP[p] = smem_u32(&Ws0[wrow * PST + colB0]);
        bLoP[p] = smem_u32(&Ws1[wrow * PST + colB0]);
    }

#pragma unroll 1
    for (int c = 0; c < 4; c++) {
        const int dc = c * 64;
        __syncthreads();
#pragma unroll
        for (int i = 0; i < 4; i++) {
            int idx = tid + i * 256;
            int row = idx >> 3;
            int v   = idx & 7;
            int gr  = row0 + row;
            int grc = (gr < rows_total) ? gr : (rows_total - 1);
            int b    = grc / cnt;
            int nloc = grc - b * cnt;
            size_t gix = ((size_t)(b * GGG + off + nloc)) * DD + dc + v * 8;
            *(uint4*)&Xs0[row * PST + v * 8] = *(const uint4*)(Xhi + gix);
            *(uint4*)&Xs1[row * PST + v * 8] = *(const uint4*)(Xlo + gix);
        }
#pragma unroll
        for (int i = 0; i < 4; i++) {
            int idx = tid + i * 256;
            int row = idx >> 3;
            int v   = idx & 7;
            size_t gix = (size_t)row * DD + dc + v * 8;
            *(uint4*)&Ws0[row * PST + v * 8] = *(const uint4*)(Whi + gix);
            *(uint4*)&Ws1[row * PST + v * 8] = *(const uint4*)(Wlo + gix);
        }
        __syncthreads();

#pragma unroll
        for (int ks = 0; ks < 4; ks++) {
            const uint32_t kadd = ks * 32;
            uint32_t ahi[2][4], alo[2][4];
#pragma unroll
            for (int mi = 0; mi < 2; mi++) {
                LDMX4(ahi[mi], aHi0 + mi * (16 * PST * 2) + kadd);
                LDMX4(alo[mi], aLo0 + mi * (16 * PST * 2) + kadd);
            }
#pragma unroll
            for (int p = 0; p < 4; p++) {
                uint32_t bh[4], bl[4];
                LDMX4(bh, bHiP[p] + kadd);
                LDMX4(bl, bLoP[p] + kadd);
#pragma unroll
                for (int mi = 0; mi < 2; mi++) {
                    MMA16816(acc[mi][2 * p],     ahi[mi], bh[0], bh[1]);
                    MMA16816(acc[mi][2 * p],     alo[mi], bh[0], bh[1]);
                    MMA16816(acc[mi][2 * p],     ahi[mi], bl[0], bl[1]);
                    MMA16816(acc[mi][2 * p + 1], ahi[mi], bh[2], bh[3]);
                    MMA16816(acc[mi][2 * p + 1], alo[mi], bh[2], bh[3]);
                    MMA16816(acc[mi][2 * p + 1], ahi[mi], bl[2], bl[3]);
                }
            }
        }
    }

#pragma unroll
    for (int mi = 0; mi < 2; mi++) {
        const int r0 = row0 + wm * 32 + mi * 16 + g;
        const int r1 = r0 + 8;
#pragma unroll
        for (int nf = 0; nf < 8; nf++) {
            const int bc = wn * 64 + nf * 8 + tig * 2;
            const int hl = bc >> 5;
            const int cc = bc & 31;
            float* dst = dstbase + (size_t)(hg * 4 + hl) * rows_total * DKK;
            if (r0 < rows_total) {
                float2 v = make_float2(acc[mi][nf][0], acc[mi][nf][1]);
                *(float2*)(dst + (size_t)r0 * DKK + cc) = v;
            }
            if (r1 < rows_total) {
                float2 v = make_float2(acc[mi][nf][2], acc[mi][nf][3]);
                *(float2*)(dst + (size_t)r1 * DKK + cc) = v;
            }
        }
    }
}

// =====================================================================
// Prep 3: K,V fp32 -> bf16 hi/lo; V transposed per hb.
// =====================================================================
__global__ __launch_bounds__(256) void cvt_kv_kernel() {
    const int kt = blockIdx.x;
    const int hb = blockIdx.y;
    const int tid = threadIdx.x;
    __shared__ float vs[64][33];

#pragma unroll
    for (int i = 0; i < 8; i++) {
        int idx = tid + i * 256;
        int key = idx >> 5;
        int dk  = idx & 31;
        size_t gsrc = ((size_t)hb * GGG + 1 + kt * 64 + key) * DKK + dk;
        float kv = g_K[gsrc];
        __nv_bfloat16 kh = __float2bfloat16(kv);
        size_t kd = ((size_t)hb * NKEY + kt * 64 + key) * DKK + dk;
        g_Kbh[kd] = kh;
        g_Kbl[kd] = __float2bfloat16(kv - __bfloat162float(kh));
        vs[key][dk] = g_V[gsrc];
    }
    __syncthreads();
#pragma unroll
    for (int i = 0; i < 8; i++) {
        int idx = tid + i * 256;
        int d = idx >> 6;
        int j = idx & 63;
        float vv = vs[j][d];
        __nv_bfloat16 vh = __float2bfloat16(vv);
        size_t o = ((size_t)hb * DKK + d) * NKEY + kt * 64 + j;
        g_Vtbh[o] = vh;
        g_Vtbl[o] = __float2bfloat16(vv - __bfloat162float(vh));
    }
}

// =====================================================================
// Kernel B (HMMA flash attention) — R13 proven, grid.x = 4 (q 0..511).
// =====================================================================
#define STQ 40
#define STK 40
#define STV 72
#define O_QMHI 0
#define O_QMLO 10240
#define O_EPHI 20480
#define O_EPLO 30720
#define O_EDHI 40960
#define O_EDLO 51200
#define O_KV   61440
#define KV_STAGE 19456
#define KV_KHI 0
#define KV_KLO 5120
#define KV_VHI 10240
#define KV_VLO 14848
#define SMEM_ATTN (O_KV + 2 * KV_STAGE)   // 100352

__device__ __forceinline__ void load_kv_tile(uint32_t sbase, int stage, int hb, int t, int tid) {
    const uint32_t dstS = sbase + O_KV + stage * KV_STAGE;
#pragma unroll
    for (int i = 0; i < 4; i++) {
        int c = tid + i * 256;            // 0..1023
        if (c < 512) {
            int half = c >> 8;            // 0 hi, 1 lo
            int cc = c & 255;
            int row = cc >> 2, qd = cc & 3;
            const __nv_bfloat16* src = (half ? g_Kbl : g_Kbh)
                + ((size_t)hb * NKEY + t * 64 + row) * DKK + qd * 8;
            uint32_t dst = dstS + (half ? KV_KLO : KV_KHI) + row * (STK * 2) + qd * 16;
            CP_ASYNC16(dst, src);
        } else {
            int half = (c >> 8) & 1;
            int cc = c & 255;
            int row = cc >> 3, qd = cc & 7;
            const __nv_bfloat16* src = (half ? g_Vtbl : g_Vtbh)
                + ((size_t)hb * DKK + row) * NKEY + t * 64 + qd * 8;
            uint32_t dst = dstS + (half ? KV_VLO : KV_VHI) + row * (STV * 2) + qd * 16;
            CP_ASYNC16(dst, src);
        }
    }
}

__global__ __launch_bounds__(256, 2) void attn_hmma_kernel() {
    extern __shared__ char sm[];
    const int qbase = blockIdx.x * 128;
    const int b     = blockIdx.y;
    const int head  = blockIdx.z;
    const int hb    = head * BBB + b;
    const int tid   = threadIdx.x;
    const int warp  = tid >> 5;
    const int lane  = tid & 31;
    const int g     = lane >> 2;
    const int tig   = lane & 3;

    const uint32_t sbase = smem_u32(sm);
    __nv_bfloat16* sQmHi = (__nv_bfloat16*)(sm + O_QMHI);
    __nv_bfloat16* sQmLo = (__nv_bfloat16*)(sm + O_QMLO);
    __nv_bfloat16* sEpHi = (__nv_bfloat16*)(sm + O_EPHI);
    __nv_bfloat16* sEpLo = (__nv_bfloat16*)(sm + O_EPLO);
    __nv_bfloat16* sEdHi = (__nv_bfloat16*)(sm + O_EDHI);
    __nv_bfloat16* sEdLo = (__nv_bfloat16*)(sm + O_EDLO);

    load_kv_tile(sbase, 0, hb, 0, tid);
    CP_COMMIT();

    // ---- prologue: convert queries into smem (scaled, hi/lo) ----
    for (int idx = tid; idx < 1024; idx += 256) {
        int row = idx >> 3, c4 = idx & 7;
        int qc = qbase + row;                 // always < GGG with grid.x = 4
        const int so = row * STQ + c4 * 4;
        {
            const float4 v = *(const float4*)(g_Q + ((size_t)hb * GGG + qc) * DKK + c4 * 4);
            uint32_t h0, l0, h1, l1;
            split2(v.x * NORMF, v.y * NORMF, h0, l0);
            split2(v.z * NORMF, v.w * NORMF, h1, l1);
            *(uint2*)(sQmHi + so) = make_uint2(h0, h1);
            *(uint2*)(sQmLo + so) = make_uint2(l0, l1);
        }
        if (qc == 0) {
            *(uint2*)(sEpHi + so) = make_uint2(0, 0);
            *(uint2*)(sEpLo + so) = make_uint2(0, 0);
            *(uint2*)(sEdHi + so) = make_uint2(0, 0);
            *(uint2*)(sEdLo + so) = make_uint2(0, 0);
        } else {
            bool pick = (qc <= NPP);
            int ppd = pick ? (qc - 1) : (qc - NPP - 1);
            size_t xo = ((size_t)hb * NPP + ppd) * DKK + c4 * 4;
            const float4 ve = *(const float4*)((pick ? g_Qx[1] : g_Qx[5]) + xo);
            const float4 vd = *(const float4*)((pick ? g_Qx[2] : g_Qx[4]) + xo);
            uint32_t h0, l0, h1, l1;
            split2(ve.x * NORMF, ve.y * NORMF, h0, l0);
            split2(ve.z * NORMF, ve.w * NORMF, h1, l1);
            *(uint2*)(sEpHi + so) = make_uint2(h0, h1);
            *(uint2*)(sEpLo + so) = make_uint2(l0, l1);
            split2(vd.x * NORMF, vd.y * NORMF, h0, l0);
            split2(vd.z * NORMF, vd.w * NORMF, h1, l1);
            *(uint2*)(sEdHi + so) = make_uint2(h0, h1);
            *(uint2*)(sEdLo + so) = make_uint2(l0, l1);
        }
    }

    // ---- init from key 0 (main query only) ----
    const int r0g = qbase + warp * 16 + g;
    const int r1g = r0g + 8;
    float m0, m1, l0, l1;
    float acc[4][4];
    {
        const float* K0 = g_K + (size_t)hb * GGG * DKK;
        const float* V0 = g_V + (size_t)hb * GGG * DKK;
        const float* q0 = g_Q + ((size_t)hb * GGG + r0g) * DKK;
        const float* q1 = g_Q + ((size_t)hb * GGG + r1g) * DKK;
        float s0 = 0.f, s1 = 0.f;
#pragma unroll
        for (int k = 0; k < DKK; k++) {
            float kk = K0[k];
            s0 = fmaf(q0[k], kk, s0);
            s1 = fmaf(q1[k], kk, s1);
        }
        m0 = s0 * NORMF;
        m1 = s1 * NORMF;
        l0 = (tig == 0) ? 1.f : 0.f;
        l1 = l0;
#pragma unroll
        for (int vf = 0; vf < 4; vf++) {
            float va = V0[vf * 8 + 2 * tig];
            float vb = V0[vf * 8 + 2 * tig + 1];
            acc[vf][0] = va; acc[vf][1] = vb;
            acc[vf][2] = va; acc[vf][3] = vb;
        }
    }

    const int rowA  = warp * 16 + (lane & 7) + ((lane >> 3) & 1) * 8;
    const int colA0 = ((lane >> 4) & 1) * 8;
    const uint32_t aoff = (uint32_t)(rowA * STQ + colA0) * 2;
    const uint32_t aQmHi = sbase + O_QMHI + aoff;
    const uint32_t aQmLo = sbase + O_QMLO + aoff;
    const uint32_t aEpHi = sbase + O_EPHI + aoff;
    const uint32_t aEpLo = sbase + O_EPLO + aoff;
    const uint32_t aEdHi = sbase + O_EDHI + aoff;
    const uint32_t aEdLo = sbase + O_EDLO + aoff;
    const int rowB  = lane & 7;
    const int colB0 = ((lane >> 3) & 1) * 8;
    const uint32_t bKoff = (uint32_t)(rowB * STK + colB0) * 2;
    const uint32_t bVoff = (uint32_t)(rowB * STV + colB0) * 2;

    const bool extra0 = (r0g != 0);

#pragma unroll 1
    for (int t = 0; t < 8; t++) {
        CP_WAIT0();
        __syncthreads();
        if (t < 7) {
            load_kv_tile(sbase, (t + 1) & 1, hb, t + 1, tid);
            CP_COMMIT();
        }

        const uint32_t stK = sbase + O_KV + (t & 1) * KV_STAGE;
        const uint32_t aEHi = (t < 4) ? aEpHi : aEdHi;
        const uint32_t aELo = (t < 4) ? aEpLo : aEdLo;

#pragma unroll
        for (int half = 0; half < 2; half++) {
            float S1[4][4], S2[4][4];
#pragma unroll
            for (int nf = 0; nf < 4; nf++)
#pragma unroll
                for (int j = 0; j < 4; j++) { S1[nf][j] = 0.f; S2[nf][j] = 0.f; }

#pragma unroll
            for (int ks = 0; ks < 2; ks++) {
                uint32_t am[4], al[4], ae[4], af[4];
                LDMX4(am, aQmHi + ks * 32);
                LDMX4(al, aQmLo + ks * 32);
                LDMX4(ae, aEHi + ks * 32);
                LDMX4(af, aELo + ks * 32);
#pragma unroll
                for (int nf = 0; nf < 4; nf++) {
                    uint32_t kaddr = stK + bKoff + (uint32_t)((half * 4 + nf) * 8) * (STK * 2) + ks * 32;
                    uint32_t kh[2], kl[2];
                    LDMX2(kh, kaddr + KV_KHI);
                    LDMX2(kl, kaddr + KV_KLO);
                    MMA16816(S1[nf], am, kh[0], kh[1]);
                    MMA16816(S1[nf], al, kh[0], kh[1]);
                    MMA16816(S1[nf], am, kl[0], kl[1]);
                    MMA16816(S2[nf], ae, kh[0], kh[1]);
                    MMA16816(S2[nf], af, kh[0], kh[1]);
                    MMA16816(S2[nf], ae, kl[0], kl[1]);
                }
            }

            float mx0 = -3.0e38f, mx1 = -3.0e38f;
#pragma unroll
            for (int nf = 0; nf < 4; nf++) {
                mx0 = fmaxf(mx0, fmaxf(S1[nf][0], S1[nf][1]));
                mx1 = fmaxf(mx1, fmaxf(S1[nf][2], S1[nf][3]));
                if (extra0) mx0 = fmaxf(mx0, fmaxf(S2[nf][0], S2[nf][1]));
                mx1 = fmaxf(mx1, fmaxf(S2[nf][2], S2[nf][3]));
            }
            mx0 = fmaxf(mx0, __shfl_xor_sync(0xffffffffu, mx0, 1));
            mx0 = fmaxf(mx0, __shfl_xor_sync(0xffffffffu, mx0, 2));
            mx1 = fmaxf(mx1, __shfl_xor_sync(0xffffffffu, mx1, 1));
            mx1 = fmaxf(mx1, __shfl_xor_sync(0xffffffffu, mx1, 2));

            float mn0 = fmaxf(m0, mx0), mn1 = fmaxf(m1, mx1);
            float c0 = __expf(m0 - mn0), c1 = __expf(m1 - mn1);
            m0 = mn0; m1 = mn1;
            l0 *= c0; l1 *= c1;
#pragma unroll
            for (int vf = 0; vf < 4; vf++) {
                acc[vf][0] *= c0; acc[vf][1] *= c0;
                acc[vf][2] *= c1; acc[vf][3] *= c1;
            }
#pragma unroll
            for (int nf = 0; nf < 4; nf++) {
                float w0 = __expf(S1[nf][0] - m0);
                float w1 = __expf(S1[nf][1] - m0);
                float w2 = __expf(S1[nf][2] - m1);
                float w3 = __expf(S1[nf][3] - m1);
                if (extra0) {
                    w0 += __expf(S2[nf][0] - m0);
                    w1 += __expf(S2[nf][1] - m0);
                }
                w2 += __expf(S2[nf][2] - m1);
                w3 += __expf(S2[nf][3] - m1);
                l0 += w0 + w1; l1 += w2 + w3;
                S1[nf][0] = w0; S1[nf][1] = w1; S1[nf][2] = w2; S1[nf][3] = w3;
            }

#pragma unroll
            for (int ks2 = 0; ks2 < 2; ks2++) {
                uint32_t ph[4], pl[4];
                split2(S1[2 * ks2][0], S1[2 * ks2][1], ph[0], pl[0]);
                split2(S1[2 * ks2][2], S1[2 * ks2][3], ph[1], pl[1]);
                split2(S1[2 * ks2 + 1][0], S1[2 * ks2 + 1][1], ph[2], pl[2]);
                split2(S1[2 * ks2 + 1][2], S1[2 * ks2 + 1][3], ph[3], pl[3]);
#pragma unroll
                for (int vf = 0; vf < 4; vf++) {
                    uint32_t vaddr = stK + bVoff + (uint32_t)(vf * 8) * (STV * 2)
                                   + (half * 2 + ks2) * 32;
                    uint32_t vh[2], vl[2];
                    LDMX2(vh, vaddr + KV_VHI);
                    LDMX2(vl, vaddr + KV_VLO);
                    MMA16816(acc[vf], ph, vh[0], vh[1]);
                    MMA16816(acc[vf], pl, vh[0], vh[1]);
                    MMA16816(acc[vf], ph, vl[0], vl[1]);
                }
            }
        }
    }

    // ---- diagonal extra logit (single key per row) ----
#pragma unroll
    for (int r = 0; r < 2; r++) {
        int qq = (r == 0) ? r0g : r1g;
        if (qq >= 1) {
            bool pick = (qq <= NPP);
            int nd = pick ? (NPP + qq) : (qq - NPP);
            int ppd = pick ? (qq - 1) : (qq - NPP - 1);
            const float* qg = (pick ? g_Qx[0] : g_Qx[3]) + ((size_t)hb * NPP + ppd) * DKK;
            const float* kk = g_K + ((size_t)hb * GGG + nd) * DKK;
            const float* vv = g_V + ((size_t)hb * GGG + nd) * DKK;
            float s = 0.f;
#pragma unroll
            for (int k = 0; k < DKK; k++) s = fmaf(qg[k], kk[k], s);
            s *= NORMF;
            float& m = (r == 0) ? m0 : m1;
            float& l = (r == 0) ? l0 : l1;
            float mn = fmaxf(m, s);
            float c = __expf(m - mn);
            m = mn;
            l *= c;
#pragma unroll
            for (int vf = 0; vf < 4; vf++) {
                acc[vf][2 * r] *= c;
                acc[vf][2 * r + 1] *= c;
            }
            float w = __expf(s - mn);
            if (tig == 0) l += w;
#pragma unroll
            for (int vf = 0; vf < 4; vf++) {
                acc[vf][2 * r]     = fmaf(w, vv[vf * 8 + 2 * tig], acc[vf][2 * r]);
                acc[vf][2 * r + 1] = fmaf(w, vv[vf * 8 + 2 * tig + 1], acc[vf][2 * r + 1]);
            }
        }
    }

    // ---- finalize: write heads as bf16 hi/lo ----
    l0 += __shfl_xor_sync(0xffffffffu, l0, 1);
    l0 += __shfl_xor_sync(0xffffffffu, l0, 2);
    l1 += __shfl_xor_sync(0xffffffffu, l1, 1);
    l1 += __shfl_xor_sync(0xffffffffu, l1, 2);
    float inv0 = 1.f / l0, inv1 = 1.f / l1;

    {
        size_t base = ((size_t)(b * GGG + r0g) * HH + head) * DKK;
#pragma unroll
        for (int vf = 0; vf < 4; vf++) {
            uint32_t hi, lo;
            split2(acc[vf][0] * inv0, acc[vf][1] * inv0, hi, lo);
            *(uint32_t*)(g_headshi + base + vf * 8 + 2 * tig) = hi;
            *(uint32_t*)(g_headslo + base + vf * 8 + 2 * tig) = lo;
        }
    }
    {
        size_t base = ((size_t)(b * GGG + r1g) * HH + head) * DKK;
#pragma unroll
        for (int vf = 0; vf < 4; vf++) {
            uint32_t hi, lo;
            split2(acc[vf][2] * inv1, acc[vf][3] * inv1, hi, lo);
            *(uint32_t*)(g_headshi + base + vf * 8 + 2 * tig) = hi;
            *(uint32_t*)(g_headslo + base + vf * 8 + 2 * tig) = lo;
        }
    }
}

// =====================================================================
// Kernel B2: scalar tail for q = 512 (one block per hb, 256 threads).
// =====================================================================
__global__ __launch_bounds__(256) void attn_tail_kernel() {
    const int hb   = blockIdx.x;        // head*BBB + b
    const int head = hb / BBB;
    const int b    = hb - head * BBB;
    const int tid  = threadIdx.x;
    const int q    = GGG - 1;           // 512, delivery, pd = 255
    const int pd   = q - NPP - 1;       // 255

    __shared__ float qm[DKK], qp[DKK], qd[DKK], qg[DKK];
    __shared__ float s1[GGG], s2[GGG];
    __shared__ float red[256];
    __shared__ float pacc[8][DKK];
    __shared__ float s_m, s_l, s_sd;

    const float* Kb = g_K + (size_t)hb * GGG * DKK;
    const float* Vb = g_V + (size_t)hb * GGG * DKK;
    const size_t xoff = ((size_t)hb * NPP + pd) * DKK;

    if (tid < DKK)          qm[tid]        = NORMF * g_Q[((size_t)hb * GGG + q) * DKK + tid];
    else if (tid < 2 * DKK) qp[tid - 32]   = NORMF * g_Qx[5][xoff + tid - 32];   // Q6 on pick keys
    else if (tid < 3 * DKK) qd[tid - 64]   = NORMF * g_Qx[4][xoff + tid - 64];   // Q5 on delivery keys
    else if (tid < 4 * DKK) qg[tid - 96]   = g_Qx[3][xoff + tid - 96];           // Q4 diag (unscaled)
    __syncthreads();

    // logits
    for (int n = tid; n < GGG; n += 256) {
        const float* kk = Kb + (size_t)n * DKK;
        float a = 0.f, e = 0.f;
        const float* qe = (n <= NPP) ? qp : qd;
#pragma unroll
        for (int k = 0; k < DKK; k++) {
            a = fmaf(qm[k], kk[k], a);
            e = fmaf(qe[k], kk[k], e);
        }
        s1[n] = a;
        s2[n] = (n >= 1) ? e : -3.0e38f;
    }
    if (tid == 0) {
        const float* kk = Kb + (size_t)(1 + pd) * DKK;   // key 256
        float s = 0.f;
#pragma unroll
        for (int k = 0; k < DKK; k++) s = fmaf(qg[k], kk[k], s);
        s_sd = s * NORMF;
    }
    __syncthreads();

    // max reduce
    float mx = -3.0e38f;
    for (int n = tid; n < GGG; n += 256) mx = fmaxf(mx, fmaxf(s1[n], s2[n]));
    if (tid == 0) mx = fmaxf(mx, s_sd);
    red[tid] = mx;
    __syncthreads();
    for (int s = 128; s > 0; s >>= 1) {
        if (tid < s) red[tid] = fmaxf(red[tid], red[tid + s]);
        __syncthreads();
    }
    if (tid == 0) s_m = red[0];
    __syncthreads();
    const float m = s_m;

    // weights + l
    float ls = 0.f;
    for (int n = tid; n < GGG; n += 256) {
        float w = __expf(s1[n] - m);
        if (n >= 1) w += __expf(s2[n] - m);
        if (n == 1 + pd) w += __expf(s_sd - m);
        s1[n] = w;
        ls += w;
    }
    red[tid] = ls;
    __syncthreads();
    for (int s = 128; s > 0; s >>= 1) {
        if (tid < s) red[tid] += red[tid + s];
        __syncthreads();
    }
    if (tid == 0) s_l = red[0];
    __syncthreads();

    // acc: thread (grp, dk)
    const int dk  = tid & 31;
    const int grp = tid >> 5;
    float a = 0.f;
    for (int n = grp; n < GGG; n += 8)
        a = fmaf(s1[n], Vb[(size_t)n * DKK + dk], a);
    pacc[grp][dk] = a;
    __syncthreads();

    if (tid < DKK) {
        float v = 0.f;
#pragma unroll
        for (int gg = 0; gg < 8; gg++) v += pacc[gg][tid];
        v /= s_l;
        __nv_bfloat16 hi = __float2bfloat16(v);
        size_t base = ((size_t)(b * GGG + q) * HH + head) * DKK + tid;
        g_headshi[base] = hi;
        g_headslo[base] = __float2bfloat16(v - __bfloat162float(hi));
    }
}

// =====================================================================
// Kernel C (HMMA): out = heads(8208x256) @ WoutT^T.  Paired-B x4 loads.
// =====================================================================
#define XS_STRIDE 72

__global__ __launch_bounds__(256) void out_hmma_kernel(float* __restrict__ out) {
    const int M = BBB * GGG;
    const int row0 = blockIdx.x * 128;
    const int col0 = blockIdx.y * 32;
    if (row0 >= M) return;

    __shared__ __nv_bfloat16 Xs[2][128][XS_STRIDE];
    __shared__ __nv_bfloat16 Ws[2][32][XS_STRIDE];

    const int tid  = threadIdx.x;
    const int warp = tid >> 5;
    const int lane = tid & 31;
    const int g    = lane >> 2;
    const int tig  = lane & 3;

    float acc[4][4];
#pragma unroll
    for (int nf = 0; nf < 4; nf++)
#pragma unroll
        for (int i = 0; i < 4; i++) acc[nf][i] = 0.f;

    const int rowA  = warp * 16 + (lane & 7) + ((lane >> 3) & 1) * 8;
    const int colA0 = ((lane >> 4) & 1) * 8;
    const uint32_t addrAhi0 = smem_u32(&Xs[0][rowA][colA0]);
    const uint32_t addrAlo0 = smem_u32(&Xs[1][rowA][colA0]);
    const int rowB  = lane & 7;
    const int colB0 = ((lane >> 3) & 1) * 8;
    const int nfsel = (lane >> 4) & 1;
    uint32_t addrBhiP[2], addrBloP[2];
#pragma unroll
    for (int p = 0; p < 2; p++) {
        addrBhiP[p] = smem_u32(&Ws[0][(2 * p + nfsel) * 8 + rowB][colB0]);
        addrBloP[p] = smem_u32(&Ws[1][(2 * p + nfsel) * 8 + rowB][colB0]);
    }

#pragma unroll 1
    for (int c = 0; c < 4; c++) {
        const int dc = c * 64;
        __syncthreads();
#pragma unroll
        for (int i = 0; i < 4; i++) {
            int idx = tid + i * 256;
            int row = idx >> 3;
            int v   = idx & 7;
            int gr  = row0 + row;
            int grc = (gr < M) ? gr : (M - 1);
            size_t gix = (size_t)grc * 256 + dc + v * 8;
            *(uint4*)&Xs[0][row][v * 8] = *(const uint4*)(g_headshi + gix);
            *(uint4*)&Xs[1][row][v * 8] = *(const uint4*)(g_headslo + gix);
        }
        {
            int row = tid >> 3;
            int v   = tid & 7;
            size_t gix = (size_t)(col0 + row) * 256 + dc + v * 8;
            *(uint4*)&Ws[0][row][v * 8] = *(const uint4*)(g_WoThi + gix);
            *(uint4*)&Ws[1][row][v * 8] = *(const uint4*)(g_WoTlo + gix);
        }
        __syncthreads();

#pragma unroll
        for (int ks = 0; ks < 4; ks++) {
            const uint32_t kadd = ks * 32;
            uint32_t ahi[4], alo[4];
            LDMX4(ahi, addrAhi0 + kadd);
            LDMX4(alo, addrAlo0 + kadd);
#pragma unroll
            for (int p = 0; p < 2; p++) {
                uint32_t bh[4], bl[4];
                LDMX4(bh, addrBhiP[p] + kadd);
                LDMX4(bl, addrBloP[p] + kadd);
                MMA16816(acc[2 * p],     ahi, bh[0], bh[1]);
                MMA16816(acc[2 * p],     alo, bh[0], bh[1]);
                MMA16816(acc[2 * p],     ahi, bl[0], bl[1]);
                MMA16816(acc[2 * p + 1], ahi, bh[2], bh[3]);
                MMA16816(acc[2 * p + 1], alo, bh[2], bh[3]);
                MMA16816(acc[2 * p + 1], ahi, bl[2], bl[3]);
            }
        }
    }

    const int r0 = row0 + warp * 16 + g;
    const int r1 = r0 + 8;
#pragma unroll
    for (int nf = 0; nf < 4; nf++) {
        const int col = col0 + nf * 8 + tig * 2;
        if (r0 < M) {
            float2 v = make_float2(acc[nf][0], acc[nf][1]);
            *(float2*)(out + (size_t)r0 * EE + col) = v;
        }
        if (r1 < M) {
            float2 v = make_float2(acc[nf][2], acc[nf][3]);
            *(float2*)(out + (size_t)r1 * EE + col) = v;
        }
    }
}

// =====================================================================
extern "C" void kernel_launch(void* const* d_in, const int* in_sizes, int n_in,
                              void* d_out, int out_size) {
    const float* q = (const float*)d_in[0];
    const float* h = (const float*)d_in[1];
    WPtrs WP;
    for (int i = 0; i < 9; i++) WP.w[i] = (const float*)d_in[2 + i];
    const float* Wout = (const float*)d_in[11];
    float* out = (float*)d_out;

    cudaFuncSetAttribute(attn_hmma_kernel, cudaFuncAttributeMaxDynamicSharedMemorySize, SMEM_ATTN);
    cudaFuncSetAttribute(proj_hmma_kernel, cudaFuncAttributeMaxDynamicSharedMemorySize, PROJ_SMEM);

    cvt_x_kernel<<<dim3((XELEMS / 8 + 255) / 256, 2), 256>>>(q, h);
    cvt_w_kernel<<<(WTELEMS + 255) / 256, 256>>>(WP);
    cvt_wout_kernel<<<(EE * HH * DKK + 255) / 256, 256>>>(Wout);

    proj_hmma_kernel<<<dim3(65, 2, 9), 256, PROJ_SMEM>>>();

    cvt_kv_kernel<<<dim3(8, HH * BBB), 256>>>();

    attn_hmma_kernel<<<dim3(4, BBB, HH), 256, SMEM_ATTN>>>();
    attn_tail_kernel<<<HH * BBB, 256>>>();

    out_hmma_kernel<<<dim3((BBB * GGG + 127) / 128, EE / 32), 256>>>(out);
}

// round 16
// speedup vs baseline: 1.0201x; 1.0090x over previous
#include <cuda_runtime.h>
#include <cuda_bf16.h>
#include <cstdint>
#include <math.h>

#define HH   8
#define DD   256
#define DKK  32
#define EE   256
#define BBB  16
#define GGG  513
#define NPP  256
#define NKEY 512

#define NORMF 0.17677669529663687f  // 1/sqrt(32)

// ---------------- scratch (static device globals; no allocation) ----------------
__device__ float g_Q[HH * BBB * GGG * DKK];
__device__ float g_K[HH * BBB * GGG * DKK];
__device__ float g_V[HH * BBB * GGG * DKK];
// g_Qx[0]=Q1(pick diag) [1]=Q2(pick->allpick) [2]=Q3(pick->alldelivery)
// g_Qx[3]=Q4(del diag)  [4]=Q5(del->alldelivery) [5]=Q6(del->allpick)
__device__ float g_Qx[6][HH * BBB * NPP * DKK];

// heads as bf16 hi/lo, [b][n][h*32+dk]
__device__ __nv_bfloat16 g_headshi[BBB * GGG * HH * DKK];
__device__ __nv_bfloat16 g_headslo[BBB * GGG * HH * DKK];

// bf16 hi/lo splits of inputs and (transposed) weights
#define XELEMS (BBB * GGG * DD)          // 2101248
__device__ __nv_bfloat16 g_qhi[XELEMS];
__device__ __nv_bfloat16 g_qlo[XELEMS];
__device__ __nv_bfloat16 g_hhi[XELEMS];
__device__ __nv_bfloat16 g_hlo[XELEMS];
// W^T: [job][head][k_out=32][d=256]
#define WTELEMS (9 * HH * DKK * DD)      // 589824
__device__ __nv_bfloat16 g_Wthi[WTELEMS];
__device__ __nv_bfloat16 g_Wtlo[WTELEMS];
// Wout^T: [e=256][f=256]
__device__ __nv_bfloat16 g_WoThi[EE * HH * DKK];
__device__ __nv_bfloat16 g_WoTlo[EE * HH * DKK];

// bf16 K (keys 1..512) and transposed V for attention MMA
__device__ __nv_bfloat16 g_Kbh[HH * BBB * NKEY * DKK];
__device__ __nv_bfloat16 g_Kbl[HH * BBB * NKEY * DKK];
__device__ __nv_bfloat16 g_Vtbh[HH * BBB * DKK * NKEY];
__device__ __nv_bfloat16 g_Vtbl[HH * BBB * DKK * NKEY];

__device__ __forceinline__ float* dst_of(int i) {
    switch (i) {
        case 0:  return g_Q;
        case 1:  return g_K;
        case 2:  return g_V;
        default: return g_Qx[i - 3];
    }
}

__device__ __forceinline__ uint32_t smem_u32(const void* p) {
    uint32_t a;
    asm("{ .reg .u64 t; cvta.to.shared.u64 t, %1; cvt.u32.u64 %0, t; }" : "=r"(a) : "l"(p));
    return a;
}

#define LDMX4(r, addr) \
    asm volatile("ldmatrix.sync.aligned.m8n8.x4.shared.b16 {%0,%1,%2,%3}, [%4];" \
        : "=r"((r)[0]), "=r"((r)[1]), "=r"((r)[2]), "=r"((r)[3]) : "r"(addr))
#define LDMX2(r, addr) \
    asm volatile("ldmatrix.sync.aligned.m8n8.x2.shared.b16 {%0,%1}, [%2];" \
        : "=r"((r)[0]), "=r"((r)[1]) : "r"(addr))

#define MMA16816(c, a, b0, b1) \
    asm volatile("mma.sync.aligned.m16n8k16.row.col.f32.bf16.bf16.f32 " \
        "{%0,%1,%2,%3}, {%4,%5,%6,%7}, {%8,%9}, {%0,%1,%2,%3};" \
        : "+f"((c)[0]), "+f"((c)[1]), "+f"((c)[2]), "+f"((c)[3]) \
        : "r"((a)[0]), "r"((a)[1]), "r"((a)[2]), "r"((a)[3]), "r"(b0), "r"(b1))

#define CP_ASYNC16(dst, src) \
    asm volatile("cp.async.cg.shared.global [%0], [%1], 16;" :: "r"(dst), "l"(src))
#define CP_COMMIT() asm volatile("cp.async.commit_group;" ::: "memory")
#define CP_WAIT0()  asm volatile("cp.async.wait_group 0;" ::: "memory")

__device__ __forceinline__ void split2(float a, float b, uint32_t& hi, uint32_t& lo) {
    __nv_bfloat16 ha = __float2bfloat16(a), hb = __float2bfloat16(b);
    __nv_bfloat162 hh = __halves2bfloat162(ha, hb);
    __nv_bfloat162 ll = __halves2bfloat162(__float2bfloat16(a - __bfloat162float(ha)),
                                           __float2bfloat16(b - __bfloat162float(hb)));
    hi = *(uint32_t*)&hh;
    lo = *(uint32_t*)&ll;
}

// =====================================================================
// Merged prep: q/h split (blocks 0..2051), W^T split (2052..4355),
// Wout^T split (4356..4611).
// =====================================================================
struct WPtrs { const float* w[9]; };

#define NB_X 1026   // XELEMS/8/256
#define NB_W 2304   // WTELEMS/256
#define NB_WO 256

__global__ __launch_bounds__(256) void cvt_all_kernel(const float* __restrict__ q,
                                                      const float* __restrict__ h,
                                                      WPtrs P,
                                                      const float* __restrict__ Wout) {
    const int blk = blockIdx.x;
    if (blk < 2 * NB_X) {
        const int which = (blk >= NB_X);
        const float* src = which ? h : q;
        __nv_bfloat16* dhi = which ? g_hhi : g_qhi;
        __nv_bfloat16* dlo = which ? g_hlo : g_qlo;
        int t = (blk - which * NB_X) * 256 + threadIdx.x;
        if (t * 8 >= XELEMS) return;
        const float4 v0 = ((const float4*)src)[t * 2];
        const float4 v1 = ((const float4*)src)[t * 2 + 1];
        float xs[8] = {v0.x, v0.y, v0.z, v0.w, v1.x, v1.y, v1.z, v1.w};
        __nv_bfloat162 hp[4], lp[4];
#pragma unroll
        for (int i = 0; i < 4; i++) {
            __nv_bfloat16 h0 = __float2bfloat16(xs[2 * i]);
            __nv_bfloat16 h1 = __float2bfloat16(xs[2 * i + 1]);
            __nv_bfloat16 l0 = __float2bfloat16(xs[2 * i] - __bfloat162float(h0));
            __nv_bfloat16 l1 = __float2bfloat16(xs[2 * i + 1] - __bfloat162float(h1));
            hp[i] = __halves2bfloat162(h0, h1);
            lp[i] = __halves2bfloat162(l0, l1);
        }
        ((uint4*)dhi)[t] = *(uint4*)hp;
        ((uint4*)dlo)[t] = *(uint4*)lp;
    } else if (blk < 2 * NB_X + NB_W) {
        int idx = (blk - 2 * NB_X) * 256 + threadIdx.x;
        int j = idx >> 16;
        int hh2 = (idx >> 13) & 7;
        int k = (idx >> 8) & 31;
        int d = idx & 255;
        float x = P.w[j][(size_t)hh2 * DD * DKK + (size_t)d * DKK + k];
        __nv_bfloat16 hi = __float2bfloat16(x);
        g_Wthi[idx] = hi;
        g_Wtlo[idx] = __float2bfloat16(x - __bfloat162float(hi));
    } else {
        int idx = (blk - 2 * NB_X - NB_W) * 256 + threadIdx.x;
        int e = idx >> 8, f = idx & 255;
        float x = Wout[(size_t)f * EE + e];
        __nv_bfloat16 hi = __float2bfloat16(x);
        g_WoThi[idx] = hi;
        g_WoTlo[idx] = __float2bfloat16(x - __bfloat162float(hi));
    }
}

// =====================================================================
// Kernel A (HMMA) v3 (proven): 128 rows x 128 cols (4 heads)/block.
// =====================================================================
#define PST 72
#define PROJ_SMEM (4 * 128 * PST * 2)   // 73728 B

__global__ __launch_bounds__(256, 2) void proj_hmma_kernel() {
    extern __shared__ __nv_bfloat16 dsm[];
    const int job  = blockIdx.z;
    const int hg   = blockIdx.y;
    const int tile = blockIdx.x;

    const int off = (job < 3) ? 0 : ((job < 6) ? 1 : (NPP + 1));
    const int cnt = (job < 3) ? GGG : NPP;
    const int rows_total = BBB * cnt;
    const int row0 = tile * 128;
    if (row0 >= rows_total) return;

    const __nv_bfloat16* Xhi = (job == 0) ? g_qhi : g_hhi;
    const __nv_bfloat16* Xlo = (job == 0) ? g_qlo : g_hlo;
    const __nv_bfloat16* Whi = g_Wthi + ((size_t)(job * HH + hg * 4)) * (DKK * DD);
    const __nv_bfloat16* Wlo = g_Wtlo + ((size_t)(job * HH + hg * 4)) * (DKK * DD);
    float* dstbase = dst_of(job);

    __nv_bfloat16* Xs0 = dsm;
    __nv_bfloat16* Xs1 = dsm + 128 * PST;
    __nv_bfloat16* Ws0 = dsm + 2 * 128 * PST;
    __nv_bfloat16* Ws1 = dsm + 3 * 128 * PST;

    const int tid  = threadIdx.x;
    const int warp = tid >> 5;
    const int lane = tid & 31;
    const int g    = lane >> 2;
    const int tig  = lane & 3;
    const int wm   = warp >> 1;
    const int wn   = warp & 1;

    float acc[2][8][4];
#pragma unroll
    for (int mi = 0; mi < 2; mi++)
#pragma unroll
        for (int nf = 0; nf < 8; nf++)
#pragma unroll
            for (int i = 0; i < 4; i++) acc[mi][nf][i] = 0.f;

    const int rowA  = wm * 32 + (lane & 7) + ((lane >> 3) & 1) * 8;
    const int colA0 = ((lane >> 4) & 1) * 8;
    const uint32_t aHi0 = smem_u32(&Xs0[rowA * PST + colA0]);
    const uint32_t aLo0 = smem_u32(&Xs1[rowA * PST + colA0]);
    const int rowB  = lane & 7;
    const int colB0 = ((lane >> 3) & 1) * 8;
    const int nfsel = (lane >> 4) & 1;
    uint32_t bHiP[4], bLoP[4];
#pragma unroll
    for (int p = 0; p < 4; p++) {
        int wrow = wn * 64 + p * 16 + nfsel * 8 + rowB;
        bHiP[p] = smem_u32(&Ws0[wrow * PST + colB0]);
        bLoP[p] = smem_u32(&Ws1[wrow * PST + colB0]);
    }

#pragma unroll 1
    for (int c = 0; c < 4; c++) {
        const int dc = c * 64;
        __syncthreads();
#pragma unroll
        for (int i = 0; i < 4; i++) {
            int idx = tid + i * 256;
            int row = idx >> 3;
            int v   = idx & 7;
            int gr  = row0 + row;
            int grc = (gr < rows_total) ? gr : (rows_total - 1);
            int b    = grc / cnt;
            int nloc = grc - b * cnt;
            size_t gix = ((size_t)(b * GGG + off + nloc)) * DD + dc + v * 8;
            *(uint4*)&Xs0[row * PST + v * 8] = *(const uint4*)(Xhi + gix);
            *(uint4*)&Xs1[row * PST + v * 8] = *(const uint4*)(Xlo + gix);
        }
#pragma unroll
        for (int i = 0; i < 4; i++) {
            int idx = tid + i * 256;
            int row = idx >> 3;
            int v   = idx & 7;
            size_t gix = (size_t)row * DD + dc + v * 8;
            *(uint4*)&Ws0[row * PST + v * 8] = *(const uint4*)(Whi + gix);
            *(uint4*)&Ws1[row * PST + v * 8] = *(const uint4*)(Wlo + gix);
        }
        __syncthreads();

#pragma unroll
        for (int ks = 0; ks < 4; ks++) {
            const uint32_t kadd = ks * 32;
            uint32_t ahi[2][4], alo[2][4];
#pragma unroll
            for (int mi = 0; mi < 2; mi++) {
                LDMX4(ahi[mi], aHi0 + mi * (16 * PST * 2) + kadd);
                LDMX4(alo[mi], aLo0 + mi * (16 * PST * 2) + kadd);
            }
#pragma unroll
            for (int p = 0; p < 4; p++) {
                uint32_t bh[4], bl[4];
                LDMX4(bh, bHiP[p] + kadd);
                LDMX4(bl, bLoP[p] + kadd);
#pragma unroll
                for (int mi = 0; mi < 2; mi++) {
                    MMA16816(acc[mi][2 * p],     ahi[mi], bh[0], bh[1]);
                    MMA16816(acc[mi][2 * p],     alo[mi], bh[0], bh[1]);
                    MMA16816(acc[mi][2 * p],     ahi[mi], bl[0], bl[1]);
                    MMA16816(acc[mi][2 * p + 1], ahi[mi], bh[2], bh[3]);
                    MMA16816(acc[mi][2 * p + 1], alo[mi], bh[2], bh[3]);
                    MMA16816(acc[mi][2 * p + 1], ahi[mi], bl[2], bl[3]);
                }
            }
        }
    }

#pragma unroll
    for (int mi = 0; mi < 2; mi++) {
        const int r0 = row0 + wm * 32 + mi * 16 + g;
        const int r1 = r0 + 8;
#pragma unroll
        for (int nf = 0; nf < 8; nf++) {
            const int bc = wn * 64 + nf * 8 + tig * 2;
            const int hl = bc >> 5;
            const int cc = bc & 31;
            float* dst = dstbase + (size_t)(hg * 4 + hl) * rows_total * DKK;
            if (r0 < rows_total) {
                float2 v = make_float2(acc[mi][nf][0], acc[mi][nf][1]);
                *(float2*)(dst + (size_t)r0 * DKK + cc) = v;
            }
            if (r1 < rows_total) {
                float2 v = make_float2(acc[mi][nf][2], acc[mi][nf][3]);
                *(float2*)(dst + (size_t)r1 * DKK + cc) = v;
            }
        }
    }
}

// =====================================================================
// Prep 3: K,V fp32 -> bf16 hi/lo; V transposed per hb.
// =====================================================================
__global__ __launch_bounds__(256) void cvt_kv_kernel() {
    const int kt = blockIdx.x;
    const int hb = blockIdx.y;
    const int tid = threadIdx.x;
    __shared__ float vs[64][33];

#pragma unroll
    for (int i = 0; i < 8; i++) {
        int idx = tid + i * 256;
        int key = idx >> 5;
        int dk  = idx & 31;
        size_t gsrc = ((size_t)hb * GGG + 1 + kt * 64 + key) * DKK + dk;
        float kv = g_K[gsrc];
        __nv_bfloat16 kh = __float2bfloat16(kv);
        size_t kd = ((size_t)hb * NKEY + kt * 64 + key) * DKK + dk;
        g_Kbh[kd] = kh;
        g_Kbl[kd] = __float2bfloat16(kv - __bfloat162float(kh));
        vs[key][dk] = g_V[gsrc];
    }
    __syncthreads();
#pragma unroll
    for (int i = 0; i < 8; i++) {
        int idx = tid + i * 256;
        int d = idx >> 6;
        int j = idx & 63;
        float vv = vs[j][d];
        __nv_bfloat16 vh = __float2bfloat16(vv);
        size_t o = ((size_t)hb * DKK + d) * NKEY + kt * 64 + j;
        g_Vtbh[o] = vh;
        g_Vtbl[o] = __float2bfloat16(vv - __bfloat162float(vh));
    }
}

// =====================================================================
// Kernel B (HMMA flash attention) — grid.x=4, cp.async 2-stage,
// hoisted Qm fragments. __launch_bounds__(256,2).
// =====================================================================
#define STQ 40
#define STK 40
#define STV 72
#define O_QMHI 0
#define O_QMLO 10240
#define O_EPHI 20480
#define O_EPLO 30720
#define O_EDHI 40960
#define O_EDLO 51200
#define O_KV   61440
#define KV_STAGE 19456
#define KV_KHI 0
#define KV_KLO 5120
#define KV_VHI 10240
#define KV_VLO 14848
#define SMEM_ATTN (O_KV + 2 * KV_STAGE)   // 100352

__device__ __forceinline__ void load_kv_tile(uint32_t sbase, int stage, int hb, int t, int tid) {
    const uint32_t dstS = sbase + O_KV + stage * KV_STAGE;
#pragma unroll
    for (int i = 0; i < 4; i++) {
        int c = tid + i * 256;            // 0..1023
        if (c < 512) {
            int half = c >> 8;            // 0 hi, 1 lo
            int cc = c & 255;
            int row = cc >> 2, qd = cc & 3;
            const __nv_bfloat16* src = (half ? g_Kbl : g_Kbh)
                + ((size_t)hb * NKEY + t * 64 + row) * DKK + qd * 8;
            uint32_t dst = dstS + (half ? KV_KLO : KV_KHI) + row * (STK * 2) + qd * 16;
            CP_ASYNC16(dst, src);
        } else {
            int half = (c >> 8) & 1;
            int cc = c & 255;
            int row = cc >> 3, qd = cc & 7;
            const __nv_bfloat16* src = (half ? g_Vtbl : g_Vtbh)
                + ((size_t)hb * DKK + row) * NKEY + t * 64 + qd * 8;
            uint32_t dst = dstS + (half ? KV_VLO : KV_VHI) + row * (STV * 2) + qd * 16;
            CP_ASYNC16(dst, src);
        }
    }
}

__global__ __launch_bounds__(256, 2) void attn_hmma_kernel() {
    extern __shared__ char sm[];
    const int qbase = blockIdx.x * 128;
    const int b     = blockIdx.y;
    const int head  = blockIdx.z;
    const int hb    = head * BBB + b;
    const int tid   = threadIdx.x;
    const int warp  = tid >> 5;
    const int lane  = tid & 31;
    const int g     = lane >> 2;
    const int tig   = lane & 3;

    const uint32_t sbase = smem_u32(sm);
    __nv_bfloat16* sQmHi = (__nv_bfloat16*)(sm + O_QMHI);
    __nv_bfloat16* sQmLo = (__nv_bfloat16*)(sm + O_QMLO);
    __nv_bfloat16* sEpHi = (__nv_bfloat16*)(sm + O_EPHI);
    __nv_bfloat16* sEpLo = (__nv_bfloat16*)(sm + O_EPLO);
    __nv_bfloat16* sEdHi = (__nv_bfloat16*)(sm + O_EDHI);
    __nv_bfloat16* sEdLo = (__nv_bfloat16*)(sm + O_EDLO);

    load_kv_tile(sbase, 0, hb, 0, tid);
    CP_COMMIT();

    // ---- prologue: convert queries into smem (scaled, hi/lo) ----
    for (int idx = tid; idx < 1024; idx += 256) {
        int row = idx >> 3, c4 = idx & 7;
        int qc = qbase + row;
        const int so = row * STQ + c4 * 4;
        {
            const float4 v = *(const float4*)(g_Q + ((size_t)hb * GGG + qc) * DKK + c4 * 4);
            uint32_t h0, l0, h1, l1;
            split2(v.x * NORMF, v.y * NORMF, h0, l0);
            split2(v.z * NORMF, v.w * NORMF, h1, l1);
            *(uint2*)(sQmHi + so) = make_uint2(h0, h1);
            *(uint2*)(sQmLo + so) = make_uint2(l0, l1);
        }
        if (qc == 0) {
            *(uint2*)(sEpHi + so) = make_uint2(0, 0);
            *(uint2*)(sEpLo + so) = make_uint2(0, 0);
            *(uint2*)(sEdHi + so) = make_uint2(0, 0);
            *(uint2*)(sEdLo + so) = make_uint2(0, 0);
        } else {
            bool pick = (qc <= NPP);
            int ppd = pick ? (qc - 1) : (qc - NPP - 1);
            size_t xo = ((size_t)hb * NPP + ppd) * DKK + c4 * 4;
            const float4 ve = *(const float4*)((pick ? g_Qx[1] : g_Qx[5]) + xo);
            const float4 vd = *(const float4*)((pick ? g_Qx[2] : g_Qx[4]) + xo);
            uint32_t h0, l0, h1, l1;
            split2(ve.x * NORMF, ve.y * NORMF, h0, l0);
            split2(ve.z * NORMF, ve.w * NORMF, h1, l1);
            *(uint2*)(sEpHi + so) = make_uint2(h0, h1);
            *(uint2*)(sEpLo + so) = make_uint2(l0, l1);
            split2(vd.x * NORMF, vd.y * NORMF, h0, l0);
            split2(vd.z * NORMF, vd.w * NORMF, h1, l1);
            *(uint2*)(sEdHi + so) = make_uint2(h0, h1);
            *(uint2*)(sEdLo + so) = make_uint2(l0, l1);
        }
    }

    // ---- init from key 0 (main query only) ----
    const int r0g = qbase + warp * 16 + g;
    const int r1g = r0g + 8;
    float m0, m1, l0, l1;
    float acc[4][4];
    {
        const float* K0 = g_K + (size_t)hb * GGG * DKK;
        const float* V0 = g_V + (size_t)hb * GGG * DKK;
        const float* q0 = g_Q + ((size_t)hb * GGG + r0g) * DKK;
        const float* q1 = g_Q + ((size_t)hb * GGG + r1g) * DKK;
        float s0 = 0.f, s1 = 0.f;
#pragma unroll
        for (int k = 0; k < DKK; k++) {
            float kk = K0[k];
            s0 = fmaf(q0[k], kk, s0);
            s1 = fmaf(q1[k], kk, s1);
        }
        m0 = s0 * NORMF;
        m1 = s1 * NORMF;
        l0 = (tig == 0) ? 1.f : 0.f;
        l1 = l0;
#pragma unroll
        for (int vf = 0; vf < 4; vf++) {
            float va = V0[vf * 8 + 2 * tig];
            float vb = V0[vf * 8 + 2 * tig + 1];
            acc[vf][0] = va; acc[vf][1] = vb;
            acc[vf][2] = va; acc[vf][3] = vb;
        }
    }

    const int rowA  = warp * 16 + (lane & 7) + ((lane >> 3) & 1) * 8;
    const int colA0 = ((lane >> 4) & 1) * 8;
    const uint32_t aoff = (uint32_t)(rowA * STQ + colA0) * 2;
    const uint32_t aQmHi = sbase + O_QMHI + aoff;
    const uint32_t aQmLo = sbase + O_QMLO + aoff;
    const uint32_t aEpHi = sbase + O_EPHI + aoff;
    const uint32_t aEpLo = sbase + O_EPLO + aoff;
    const uint32_t aEdHi = sbase + O_EDHI + aoff;
    const uint32_t aEdLo = sbase + O_EDLO + aoff;
    const int rowB  = lane & 7;
    const int colB0 = ((lane >> 3) & 1) * 8;
    const uint32_t bKoff = (uint32_t)(rowB * STK + colB0) * 2;
    const uint32_t bVoff = (uint32_t)(rowB * STV + colB0) * 2;

    const bool extra0 = (r0g != 0);

    // ---- hoist Qm fragments (constant across all tiles) ----
    __syncthreads();
    uint32_t fQmHi[2][4], fQmLo[2][4];
    LDMX4(fQmHi[0], aQmHi);
    LDMX4(fQmHi[1], aQmHi + 32);
    LDMX4(fQmLo[0], aQmLo);
    LDMX4(fQmLo[1], aQmLo + 32);

#pragma unroll 1
    for (int t = 0; t < 8; t++) {
        CP_WAIT0();
        __syncthreads();
        if (t < 7) {
            load_kv_tile(sbase, (t + 1) & 1, hb, t + 1, tid);
            CP_COMMIT();
        }

        const uint32_t stK = sbase + O_KV + (t & 1) * KV_STAGE;
        const uint32_t aEHi = (t < 4) ? aEpHi : aEdHi;
        const uint32_t aELo = (t < 4) ? aEpLo : aEdLo;

#pragma unroll
        for (int half = 0; half < 2; half++) {
            float S1[4][4], S2[4][4];
#pragma unroll
            for (int nf = 0; nf < 4; nf++)
#pragma unroll
                for (int j = 0; j < 4; j++) { S1[nf][j] = 0.f; S2[nf][j] = 0.f; }

#pragma unroll
            for (int ks = 0; ks < 2; ks++) {
                uint32_t ae[4], af[4];
                LDMX4(ae, aEHi + ks * 32);
                LDMX4(af, aELo + ks * 32);
#pragma unroll
                for (int nf = 0; nf < 4; nf++) {
                    uint32_t kaddr = stK + bKoff + (uint32_t)((half * 4 + nf) * 8) * (STK * 2) + ks * 32;
                    uint32_t kh[2], kl[2];
                    LDMX2(kh, kaddr + KV_KHI);
                    LDMX2(kl, kaddr + KV_KLO);
                    MMA16816(S1[nf], fQmHi[ks], kh[0], kh[1]);
                    MMA16816(S1[nf], fQmLo[ks], kh[0], kh[1]);
                    MMA16816(S1[nf], fQmHi[ks], kl[0], kl[1]);
                    MMA16816(S2[nf], ae, kh[0], kh[1]);
                    MMA16816(S2[nf], af, kh[0], kh[1]);
                    MMA16816(S2[nf], ae, kl[0], kl[1]);
                }
            }

            float mx0 = -3.0e38f, mx1 = -3.0e38f;
#pragma unroll
            for (int nf = 0; nf < 4; nf++) {
                mx0 = fmaxf(mx0, fmaxf(S1[nf][0], S1[nf][1]));
                mx1 = fmaxf(mx1, fmaxf(S1[nf][2], S1[nf][3]));
                if (extra0) mx0 = fmaxf(mx0, fmaxf(S2[nf][0], S2[nf][1]));
                mx1 = fmaxf(mx1, fmaxf(S2[nf][2], S2[nf][3]));
            }
            mx0 = fmaxf(mx0, __shfl_xor_sync(0xffffffffu, mx0, 1));
            mx0 = fmaxf(mx0, __shfl_xor_sync(0xffffffffu, mx0, 2));
            mx1 = fmaxf(mx1, __shfl_xor_sync(0xffffffffu, mx1, 1));
            mx1 = fmaxf(mx1, __shfl_xor_sync(0xffffffffu, mx1, 2));

            float mn0 = fmaxf(m0, mx0), mn1 = fmaxf(m1, mx1);
            float c0 = __expf(m0 - mn0), c1 = __expf(m1 - mn1);
            m0 = mn0; m1 = mn1;
            l0 *= c0; l1 *= c1;
#pragma unroll
            for (int vf = 0; vf < 4; vf++) {
                acc[vf][0] *= c0; acc[vf][1] *= c0;
                acc[vf][2] *= c1; acc[vf][3] *= c1;
            }
#pragma unroll
            for (int nf = 0; nf < 4; nf++) {
                float w0 = __expf(S1[nf][0] - m0);
                float w1 = __expf(S1[nf][1] - m0);
                float w2 = __expf(S1[nf][2] - m1);
                float w3 = __expf(S1[nf][3] - m1);
                if (extra0) {
                    w0 += __expf(S2[nf][0] - m0);
                    w1 += __expf(S2[nf][1] - m0);
                }
                w2 += __expf(S2[nf][2] - m1);
                w3 += __expf(S2[nf][3] - m1);
                l0 += w0 + w1; l1 += w2 + w3;
                S1[nf][0] = w0; S1[nf][1] = w1; S1[nf][2] = w2; S1[nf][3] = w3;
            }

#pragma unroll
            for (int ks2 = 0; ks2 < 2; ks2++) {
                uint32_t ph[4], pl[4];
                split2(S1[2 * ks2][0], S1[2 * ks2][1], ph[0], pl[0]);
                split2(S1[2 * ks2][2], S1[2 * ks2][3], ph[1], pl[1]);
                split2(S1[2 * ks2 + 1][0], S1[2 * ks2 + 1][1], ph[2], pl[2]);
                split2(S1[2 * ks2 + 1][2], S1[2 * ks2 + 1][3], ph[3], pl[3]);
#pragma unroll
                for (int vf = 0; vf < 4; vf++) {
                    uint32_t vaddr = stK + bVoff + (uint32_t)(vf * 8) * (STV * 2)
                                   + (half * 2 + ks2) * 32;
                    uint32_t vh[2], vl[2];
                    LDMX2(vh, vaddr + KV_VHI);
                    LDMX2(vl, vaddr + KV_VLO);
                    MMA16816(acc[vf], ph, vh[0], vh[1]);
                    MMA16816(acc[vf], pl, vh[0], vh[1]);
                    MMA16816(acc[vf], ph, vl[0], vl[1]);
                }
            }
        }
    }

    // ---- diagonal extra logit (single key per row) ----
#pragma unroll
    for (int r = 0; r < 2; r++) {
        int qq = (r == 0) ? r0g : r1g;
        if (qq >= 1) {
            bool pick = (qq <= NPP);
            int nd = pick ? (NPP + qq) : (qq - NPP);
            int ppd = pick ? (qq - 1) : (qq - NPP - 1);
            const float* qg = (pick ? g_Qx[0] : g_Qx[3]) + ((size_t)hb * NPP + ppd) * DKK;
            const float* kk = g_K + ((size_t)hb * GGG + nd) * DKK;
            const float* vv = g_V + ((size_t)hb * GGG + nd) * DKK;
            float s = 0.f;
#pragma unroll
            for (int k = 0; k < DKK; k++) s = fmaf(qg[k], kk[k], s);
            s *= NORMF;
            float& m = (r == 0) ? m0 : m1;
            float& l = (r == 0) ? l0 : l1;
            float mn = fmaxf(m, s);
            float c = __expf(m - mn);
            m = mn;
            l *= c;
#pragma unroll
            for (int vf = 0; vf < 4; vf++) {
                acc[vf][2 * r] *= c;
                acc[vf][2 * r + 1] *= c;
            }
            float w = __expf(s - mn);
            if (tig == 0) l += w;
#pragma unroll
            for (int vf = 0; vf < 4; vf++) {
                acc[vf][2 * r]     = fmaf(w, vv[vf * 8 + 2 * tig], acc[vf][2 * r]);
                acc[vf][2 * r + 1] = fmaf(w, vv[vf * 8 + 2 * tig + 1], acc[vf][2 * r + 1]);
            }
        }
    }

    // ---- finalize: write heads as bf16 hi/lo ----
    l0 += __shfl_xor_sync(0xffffffffu, l0, 1);
    l0 += __shfl_xor_sync(0xffffffffu, l0, 2);
    l1 += __shfl_xor_sync(0xffffffffu, l1, 1);
    l1 += __shfl_xor_sync(0xffffffffu, l1, 2);
    float inv0 = 1.f / l0, inv1 = 1.f / l1;

    {
        size_t base = ((size_t)(b * GGG + r0g) * HH + head) * DKK;
#pragma unroll
        for (int vf = 0; vf < 4; vf++) {
            uint32_t hi, lo;
            split2(acc[vf][0] * inv0, acc[vf][1] * inv0, hi, lo);
            *(uint32_t*)(g_headshi + base + vf * 8 + 2 * tig) = hi;
            *(uint32_t*)(g_headslo + base + vf * 8 + 2 * tig) = lo;
        }
    }
    {
        size_t base = ((size_t)(b * GGG + r1g) * HH + head) * DKK;
#pragma unroll
        for (int vf = 0; vf < 4; vf++) {
            uint32_t hi, lo;
            split2(acc[vf][2] * inv1, acc[vf][3] * inv1, hi, lo);
            *(uint32_t*)(g_headshi + base + vf * 8 + 2 * tig) = hi;
            *(uint32_t*)(g_headslo + base + vf * 8 + 2 * tig) = lo;
        }
    }
}

// =====================================================================
// Kernel B2: scalar tail for q = 512 (one block per hb, 256 threads).
// =====================================================================
__global__ __launch_bounds__(256) void attn_tail_kernel() {
    const int hb   = blockIdx.x;
    const int head = hb / BBB;
    const int b    = hb - head * BBB;
    const int tid  = threadIdx.x;
    const int q    = GGG - 1;
    const int pd   = q - NPP - 1;

    __shared__ float qm[DKK], qp[DKK], qd[DKK], qg[DKK];
    __shared__ float s1[GGG], s2[GGG];
    __shared__ float red[256];
    __shared__ float pacc[8][DKK];
    __shared__ float s_m, s_l, s_sd;

    const float* Kb = g_K + (size_t)hb * GGG * DKK;
    const float* Vb = g_V + (size_t)hb * GGG * DKK;
    const size_t xoff = ((size_t)hb * NPP + pd) * DKK;

    if (tid < DKK)          qm[tid]        = NORMF * g_Q[((size_t)hb * GGG + q) * DKK + tid];
    else if (tid < 2 * DKK) qp[tid - 32]   = NORMF * g_Qx[5][xoff + tid - 32];
    else if (tid < 3 * DKK) qd[tid - 64]   = NORMF * g_Qx[4][xoff + tid - 64];
    else if (tid < 4 * DKK) qg[tid - 96]   = g_Qx[3][xoff + tid - 96];
    __syncthreads();

    for (int n = tid; n < GGG; n += 256) {
        const float* kk = Kb + (size_t)n * DKK;
        float a = 0.f, e = 0.f;
        const float* qe = (n <= NPP) ? qp : qd;
#pragma unroll
        for (int k = 0; k < DKK; k++) {
            a = fmaf(qm[k], kk[k], a);
            e = fmaf(qe[k], kk[k], e);
        }
        s1[n] = a;
        s2[n] = (n >= 1) ? e : -3.0e38f;
    }
    if (tid == 0) {
        const float* kk = Kb + (size_t)(1 + pd) * DKK;
        float s = 0.f;
#pragma unroll
        for (int k = 0; k < DKK; k++) s = fmaf(qg[k], kk[k], s);
        s_sd = s * NORMF;
    }
    __syncthreads();

    float mx = -3.0e38f;
    for (int n = tid; n < GGG; n += 256) mx = fmaxf(mx, fmaxf(s1[n], s2[n]));
    if (tid == 0) mx = fmaxf(mx, s_sd);
    red[tid] = mx;
    __syncthreads();
    for (int s = 128; s > 0; s >>= 1) {
        if (tid < s) red[tid] = fmaxf(red[tid], red[tid + s]);
        __syncthreads();
    }
    if (tid == 0) s_m = red[0];
    __syncthreads();
    const float m = s_m;

    float ls = 0.f;
    for (int n = tid; n < GGG; n += 256) {
        float w = __expf(s1[n] - m);
        if (n >= 1) w += __expf(s2[n] - m);
        if (n == 1 + pd) w += __expf(s_sd - m);
        s1[n] = w;
        ls += w;
    }
    red[tid] = ls;
    __syncthreads();
    for (int s = 128; s > 0; s >>= 1) {
        if (tid < s) red[tid] += red[tid + s];
        __syncthreads();
    }
    if (tid == 0) s_l = red[0];
    __syncthreads();

    const int dk  = tid & 31;
    const int grp = tid >> 5;
    float a = 0.f;
    for (int n = grp; n < GGG; n += 8)
        a = fmaf(s1[n], Vb[(size_t)n * DKK + dk], a);
    pacc[grp][dk] = a;
    __syncthreads();

    if (tid < DKK) {
        float v = 0.f;
#pragma unroll
        for (int gg = 0; gg < 8; gg++) v += pacc[gg][tid];
        v /= s_l;
        __nv_bfloat16 hi = __float2bfloat16(v);
        size_t base = ((size_t)(b * GGG + q) * HH + head) * DKK + tid;
        g_headshi[base] = hi;
        g_headslo[base] = __float2bfloat16(v - __bfloat162float(hi));
    }
}

// =====================================================================
// Kernel C (HMMA): out = heads(8208x256) @ WoutT^T.  (256,2).
// =====================================================================
#define XS_STRIDE 72

__global__ __launch_bounds__(256, 2) void out_hmma_kernel(float* __restrict__ out) {
    const int M = BBB * GGG;
    const int row0 = blockIdx.x * 128;
    const int col0 = blockIdx.y * 32;
    if (row0 >= M) return;

    __shared__ __nv_bfloat16 Xs[2][128][XS_STRIDE];
    __shared__ __nv_bfloat16 Ws[2][32][XS_STRIDE];

    const int tid  = threadIdx.x;
    const int warp = tid >> 5;
    const int lane = tid & 31;
    const int g    = lane >> 2;
    const int tig  = lane & 3;

    float acc[4][4];
#pragma unroll
    for (int nf = 0; nf < 4; nf++)
#pragma unroll
        for (int i = 0; i < 4; i++) acc[nf][i] = 0.f;

    const int rowA  = warp * 16 + (lane & 7) + ((lane >> 3) & 1) * 8;
    const int colA0 = ((lane >> 4) & 1) * 8;
    const uint32_t addrAhi0 = smem_u32(&Xs[0][rowA][colA0]);
    const uint32_t addrAlo0 = smem_u32(&Xs[1][rowA][colA0]);
    const int rowB  = lane & 7;
    const int colB0 = ((lane >> 3) & 1) * 8;
    const int nfsel = (lane >> 4) & 1;
    uint32_t addrBhiP[2], addrBloP[2];
#pragma unroll
    for (int p = 0; p < 2; p++) {
        addrBhiP[p] = smem_u32(&Ws[0][(2 * p + nfsel) * 8 + rowB][colB0]);
        addrBloP[p] = smem_u32(&Ws[1][(2 * p + nfsel) * 8 + rowB][colB0]);
    }

#pragma unroll 1
    for (int c = 0; c < 4; c++) {
        const int dc = c * 64;
        __syncthreads();
#pragma unroll
        for (int i = 0; i < 4; i++) {
            int idx = tid + i * 256;
            int row = idx >> 3;
            int v   = idx & 7;
            int gr  = row0 + row;
            int grc = (gr < M) ? gr : (M - 1);
            size_t gix = (size_t)grc * 256 + dc + v * 8;
            *(uint4*)&Xs[0][row][v * 8] = *(const uint4*)(g_headshi + gix);
            *(uint4*)&Xs[1][row][v * 8] = *(const uint4*)(g_headslo + gix);
        }
        {
            int row = tid >> 3;
            int v   = tid & 7;
            size_t gix = (size_t)(col0 + row) * 256 + dc + v * 8;
            *(uint4*)&Ws[0][row][v * 8] = *(const uint4*)(g_WoThi + gix);
            *(uint4*)&Ws[1][row][v * 8] = *(const uint4*)(g_WoTlo + gix);
        }
        __syncthreads();

#pragma unroll
        for (int ks = 0; ks < 4; ks++) {
            const uint32_t kadd = ks * 32;
            uint32_t ahi[4], alo[4];
            LDMX4(ahi, addrAhi0 + kadd);
            LDMX4(alo, addrAlo0 + kadd);
#pragma unroll
            for (int p = 0; p < 2; p++) {
                uint32_t bh[4], bl[4];
                LDMX4(bh, addrBhiP[p] + kadd);
                LDMX4(bl, addrBloP[p] + kadd);
                MMA16816(acc[2 * p],     ahi, bh[0], bh[1]);
                MMA16816(acc[2 * p],     alo, bh[0], bh[1]);
                MMA16816(acc[2 * p],     ahi, bl[0], bl[1]);
                MMA16816(acc[2 * p + 1], ahi, bh[2], bh[3]);
                MMA16816(acc[2 * p + 1], alo, bh[2], bh[3]);
                MMA16816(acc[2 * p + 1], ahi, bl[2], bl[3]);
            }
        }
    }

    const int r0 = row0 + warp * 16 + g;
    const int r1 = r0 + 8;
#pragma unroll
    for (int nf = 0; nf < 4; nf++) {
        const int col = col0 + nf * 8 + tig * 2;
        if (r0 < M) {
            float2 v = make_float2(acc[nf][0], acc[nf][1]);
            *(float2*)(out + (size_t)r0 * EE + col) = v;
        }
        if (r1 < M) {
            float2 v = make_float2(acc[nf][2], acc[nf][3]);
            *(float2*)(out + (size_t)r1 * EE + col) = v;
        }
    }
}

// =====================================================================
extern "C" void kernel_launch(void* const* d_in, const int* in_sizes, int n_in,
                              void* d_out, int out_size) {
    const float* q = (const float*)d_in[0];
    const float* h = (const float*)d_in[1];
    WPtrs WP;
    for (int i = 0; i < 9; i++) WP.w[i] = (const float*)d_in[2 + i];
    const float* Wout = (const float*)d_in[11];
    float* out = (float*)d_out;

    cudaFuncSetAttribute(attn_hmma_kernel, cudaFuncAttributeMaxDynamicSharedMemorySize, SMEM_ATTN);
    cudaFuncSetAttribute(proj_hmma_kernel, cudaFuncAttributeMaxDynamicSharedMemorySize, PROJ_SMEM);

    cvt_all_kernel<<<2 * NB_X + NB_W + NB_WO, 256>>>(q, h, WP, Wout);

    proj_hmma_kernel<<<dim3(65, 2, 9), 256, PROJ_SMEM>>>();

    cvt_kv_kernel<<<dim3(8, HH * BBB), 256>>>();

    attn_hmma_kernel<<<dim3(4, BBB, HH), 256, SMEM_ATTN>>>();
    attn_tail_kernel<<<HH * BBB, 256>>>();

    out_hmma_kernel<<<dim3((BBB * GGG + 127) / 128, EE / 32), 256>>>(out);
}

// round 17
// speedup vs baseline: 1.0457x; 1.0251x over previous
#include <cuda_runtime.h>
#include <cuda_bf16.h>
#include <cstdint>
#include <math.h>

#define HH   8
#define DD   256
#define DKK  32
#define EE   256
#define BBB  16
#define GGG  513
#define NPP  256
#define NKEY 512

#define NORMF 0.17677669529663687f  // 1/sqrt(32)
#define MCONST 15.0f                // fixed softmax max-shift (scores bounded ~|10|)

// ---------------- scratch (static device globals; no allocation) ----------------
__device__ float g_Q[HH * BBB * GGG * DKK];
__device__ float g_K[HH * BBB * GGG * DKK];
__device__ float g_V[HH * BBB * GGG * DKK];
// g_Qx[0]=Q1(pick diag) [1]=Q2(pick->allpick) [2]=Q3(pick->alldelivery)
// g_Qx[3]=Q4(del diag)  [4]=Q5(del->alldelivery) [5]=Q6(del->allpick)
__device__ float g_Qx[6][HH * BBB * NPP * DKK];

// heads as bf16 hi/lo, [b][n][h*32+dk]
__device__ __nv_bfloat16 g_headshi[BBB * GGG * HH * DKK];
__device__ __nv_bfloat16 g_headslo[BBB * GGG * HH * DKK];

// bf16 hi/lo splits of inputs and (transposed) weights
#define XELEMS (BBB * GGG * DD)          // 2101248
__device__ __nv_bfloat16 g_qhi[XELEMS];
__device__ __nv_bfloat16 g_qlo[XELEMS];
__device__ __nv_bfloat16 g_hhi[XELEMS];
__device__ __nv_bfloat16 g_hlo[XELEMS];
// W^T: [job][head][k_out=32][d=256]
#define WTELEMS (9 * HH * DKK * DD)      // 589824
__device__ __nv_bfloat16 g_Wthi[WTELEMS];
__device__ __nv_bfloat16 g_Wtlo[WTELEMS];
// Wout^T: [e=256][f=256]
__device__ __nv_bfloat16 g_WoThi[EE * HH * DKK];
__device__ __nv_bfloat16 g_WoTlo[EE * HH * DKK];

// bf16 K (keys 1..512) and transposed V for attention MMA
__device__ __nv_bfloat16 g_Kbh[HH * BBB * NKEY * DKK];
__device__ __nv_bfloat16 g_Kbl[HH * BBB * NKEY * DKK];
__device__ __nv_bfloat16 g_Vtbh[HH * BBB * DKK * NKEY];
__device__ __nv_bfloat16 g_Vtbl[HH * BBB * DKK * NKEY];

__device__ __forceinline__ float* dst_of(int i) {
    switch (i) {
        case 0:  return g_Q;
        case 1:  return g_K;
        case 2:  return g_V;
        default: return g_Qx[i - 3];
    }
}

__device__ __forceinline__ uint32_t smem_u32(const void* p) {
    uint32_t a;
    asm("{ .reg .u64 t; cvta.to.shared.u64 t, %1; cvt.u32.u64 %0, t; }" : "=r"(a) : "l"(p));
    return a;
}

#define LDMX4(r, addr) \
    asm volatile("ldmatrix.sync.aligned.m8n8.x4.shared.b16 {%0,%1,%2,%3}, [%4];" \
        : "=r"((r)[0]), "=r"((r)[1]), "=r"((r)[2]), "=r"((r)[3]) : "r"(addr))
#define LDMX2(r, addr) \
    asm volatile("ldmatrix.sync.aligned.m8n8.x2.shared.b16 {%0,%1}, [%2];" \
        : "=r"((r)[0]), "=r"((r)[1]) : "r"(addr))

#define MMA16816(c, a, b0, b1) \
    asm volatile("mma.sync.aligned.m16n8k16.row.col.f32.bf16.bf16.f32 " \
        "{%0,%1,%2,%3}, {%4,%5,%6,%7}, {%8,%9}, {%0,%1,%2,%3};" \
        : "+f"((c)[0]), "+f"((c)[1]), "+f"((c)[2]), "+f"((c)[3]) \
        : "r"((a)[0]), "r"((a)[1]), "r"((a)[2]), "r"((a)[3]), "r"(b0), "r"(b1))

#define CP_ASYNC16(dst, src) \
    asm volatile("cp.async.cg.shared.global [%0], [%1], 16;" :: "r"(dst), "l"(src))
#define CP_COMMIT() asm volatile("cp.async.commit_group;" ::: "memory")
#define CP_WAIT0()  asm volatile("cp.async.wait_group 0;" ::: "memory")

__device__ __forceinline__ void split2(float a, float b, uint32_t& hi, uint32_t& lo) {
    __nv_bfloat16 ha = __float2bfloat16(a), hb = __float2bfloat16(b);
    __nv_bfloat162 hh = __halves2bfloat162(ha, hb);
    __nv_bfloat162 ll = __halves2bfloat162(__float2bfloat16(a - __bfloat162float(ha)),
                                           __float2bfloat16(b - __bfloat162float(hb)));
    hi = *(uint32_t*)&hh;
    lo = *(uint32_t*)&ll;
}

// =====================================================================
// Merged prep: q/h split, W^T split, Wout^T split.
// =====================================================================
struct WPtrs { const float* w[9]; };

#define NB_X 1026
#define NB_W 2304
#define NB_WO 256

__global__ __launch_bounds__(256) void cvt_all_kernel(const float* __restrict__ q,
                                                      const float* __restrict__ h,
                                                      WPtrs P,
                                                      const float* __restrict__ Wout) {
    const int blk = blockIdx.x;
    if (blk < 2 * NB_X) {
        const int which = (blk >= NB_X);
        const float* src = which ? h : q;
        __nv_bfloat16* dhi = which ? g_hhi : g_qhi;
        __nv_bfloat16* dlo = which ? g_hlo : g_qlo;
        int t = (blk - which * NB_X) * 256 + threadIdx.x;
        if (t * 8 >= XELEMS) return;
        const float4 v0 = ((const float4*)src)[t * 2];
        const float4 v1 = ((const float4*)src)[t * 2 + 1];
        float xs[8] = {v0.x, v0.y, v0.z, v0.w, v1.x, v1.y, v1.z, v1.w};
        __nv_bfloat162 hp[4], lp[4];
#pragma unroll
        for (int i = 0; i < 4; i++) {
            __nv_bfloat16 h0 = __float2bfloat16(xs[2 * i]);
            __nv_bfloat16 h1 = __float2bfloat16(xs[2 * i + 1]);
            __nv_bfloat16 l0 = __float2bfloat16(xs[2 * i] - __bfloat162float(h0));
            __nv_bfloat16 l1 = __float2bfloat16(xs[2 * i + 1] - __bfloat162float(h1));
            hp[i] = __halves2bfloat162(h0, h1);
            lp[i] = __halves2bfloat162(l0, l1);
        }
        ((uint4*)dhi)[t] = *(uint4*)hp;
        ((uint4*)dlo)[t] = *(uint4*)lp;
    } else if (blk < 2 * NB_X + NB_W) {
        int idx = (blk - 2 * NB_X) * 256 + threadIdx.x;
        int j = idx >> 16;
        int hh2 = (idx >> 13) & 7;
        int k = (idx >> 8) & 31;
        int d = idx & 255;
        float x = P.w[j][(size_t)hh2 * DD * DKK + (size_t)d * DKK + k];
        __nv_bfloat16 hi = __float2bfloat16(x);
        g_Wthi[idx] = hi;
        g_Wtlo[idx] = __float2bfloat16(x - __bfloat162float(hi));
    } else {
        int idx = (blk - 2 * NB_X - NB_W) * 256 + threadIdx.x;
        int e = idx >> 8, f = idx & 255;
        float x = Wout[(size_t)f * EE + e];
        __nv_bfloat16 hi = __float2bfloat16(x);
        g_WoThi[idx] = hi;
        g_WoTlo[idx] = __float2bfloat16(x - __bfloat162float(hi));
    }
}

// =====================================================================
// Kernel A (HMMA) v3 (proven): 128 rows x 128 cols (4 heads)/block.
// =====================================================================
#define PST 72
#define PROJ_SMEM (4 * 128 * PST * 2)   // 73728 B

__global__ __launch_bounds__(256, 2) void proj_hmma_kernel() {
    extern __shared__ __nv_bfloat16 dsm[];
    const int job  = blockIdx.z;
    const int hg   = blockIdx.y;
    const int tile = blockIdx.x;

    const int off = (job < 3) ? 0 : ((job < 6) ? 1 : (NPP + 1));
    const int cnt = (job < 3) ? GGG : NPP;
    const int rows_total = BBB * cnt;
    const int row0 = tile * 128;
    if (row0 >= rows_total) return;

    const __nv_bfloat16* Xhi = (job == 0) ? g_qhi : g_hhi;
    const __nv_bfloat16* Xlo = (job == 0) ? g_qlo : g_hlo;
    const __nv_bfloat16* Whi = g_Wthi + ((size_t)(job * HH + hg * 4)) * (DKK * DD);
    const __nv_bfloat16* Wlo = g_Wtlo + ((size_t)(job * HH + hg * 4)) * (DKK * DD);
    float* dstbase = dst_of(job);

    __nv_bfloat16* Xs0 = dsm;
    __nv_bfloat16* Xs1 = dsm + 128 * PST;
    __nv_bfloat16* Ws0 = dsm + 2 * 128 * PST;
    __nv_bfloat16* Ws1 = dsm + 3 * 128 * PST;

    const int tid  = threadIdx.x;
    const int warp = tid >> 5;
    const int lane = tid & 31;
    const int g    = lane >> 2;
    const int tig  = lane & 3;
    const int wm   = warp >> 1;
    const int wn   = warp & 1;

    float acc[2][8][4];
#pragma unroll
    for (int mi = 0; mi < 2; mi++)
#pragma unroll
        for (int nf = 0; nf < 8; nf++)
#pragma unroll
            for (int i = 0; i < 4; i++) acc[mi][nf][i] = 0.f;

    const int rowA  = wm * 32 + (lane & 7) + ((lane >> 3) & 1) * 8;
    const int colA0 = ((lane >> 4) & 1) * 8;
    const uint32_t aHi0 = smem_u32(&Xs0[rowA * PST + colA0]);
    const uint32_t aLo0 = smem_u32(&Xs1[rowA * PST + colA0]);
    const int rowB  = lane & 7;
    const int colB0 = ((lane >> 3) & 1) * 8;
    const int nfsel = (lane >> 4) & 1;
    uint32_t bHiP[4], bLoP[4];
#pragma unroll
    for (int p = 0; p < 4; p++) {
        int wrow = wn * 64 + p * 16 + nfsel * 8 + rowB;
        bHiP[p] = smem_u32(&Ws0[wrow * PST + colB0]);
        bLoP[p] = smem_u32(&Ws1[wrow * PST + colB0]);
    }

#pragma unroll 1
    for (int c = 0; c < 4; c++) {
        const int dc = c * 64;
        __syncthreads();
#pragma unroll
        for (int i = 0; i < 4; i++) {
            int idx = tid + i * 256;
            int row = idx >> 3;
            int v   = idx & 7;
            int gr  = row0 + row;
            int grc = (gr < rows_total) ? gr : (rows_total - 1);
            int b    = grc / cnt;
            int nloc = grc - b * cnt;
            size_t gix = ((size_t)(b * GGG + off + nloc)) * DD + dc + v * 8;
            *(uint4*)&Xs0[row * PST + v * 8] = *(const uint4*)(Xhi + gix);
            *(uint4*)&Xs1[row * PST + v * 8] = *(const uint4*)(Xlo + gix);
        }
#pragma unroll
        for (int i = 0; i < 4; i++) {
            int idx = tid + i * 256;
            int row = idx >> 3;
            int v   = idx & 7;
            size_t gix = (size_t)row * DD + dc + v * 8;
            *(uint4*)&Ws0[row * PST + v * 8] = *(const uint4*)(Whi + gix);
            *(uint4*)&Ws1[row * PST + v * 8] = *(const uint4*)(Wlo + gix);
        }
        __syncthreads();

#pragma unroll
        for (int ks = 0; ks < 4; ks++) {
            const uint32_t kadd = ks * 32;
            uint32_t ahi[2][4], alo[2][4];
#pragma unroll
            for (int mi = 0; mi < 2; mi++) {
                LDMX4(ahi[mi], aHi0 + mi * (16 * PST * 2) + kadd);
                LDMX4(alo[mi], aLo0 + mi * (16 * PST * 2) + kadd);
            }
#pragma unroll
            for (int p = 0; p < 4; p++) {
                uint32_t bh[4], bl[4];
                LDMX4(bh, bHiP[p] + kadd);
                LDMX4(bl, bLoP[p] + kadd);
#pragma unroll
                for (int mi = 0; mi < 2; mi++) {
                    MMA16816(acc[mi][2 * p],     ahi[mi], bh[0], bh[1]);
                    MMA16816(acc[mi][2 * p],     alo[mi], bh[0], bh[1]);
                    MMA16816(acc[mi][2 * p],     ahi[mi], bl[0], bl[1]);
                    MMA16816(acc[mi][2 * p + 1], ahi[mi], bh[2], bh[3]);
                    MMA16816(acc[mi][2 * p + 1], alo[mi], bh[2], bh[3]);
                    MMA16816(acc[mi][2 * p + 1], ahi[mi], bl[2], bl[3]);
                }
            }
        }
    }

#pragma unroll
    for (int mi = 0; mi < 2; mi++) {
        const int r0 = row0 + wm * 32 + mi * 16 + g;
        const int r1 = r0 + 8;
#pragma unroll
        for (int nf = 0; nf < 8; nf++) {
            const int bc = wn * 64 + nf * 8 + tig * 2;
            const int hl = bc >> 5;
            const int cc = bc & 31;
            float* dst = dstbase + (size_t)(hg * 4 + hl) * rows_total * DKK;
            if (r0 < rows_total) {
                float2 v = make_float2(acc[mi][nf][0], acc[mi][nf][1]);
                *(float2*)(dst + (size_t)r0 * DKK + cc) = v;
            }
            if (r1 < rows_total) {
                float2 v = make_float2(acc[mi][nf][2], acc[mi][nf][3]);
                *(float2*)(dst + (size_t)r1 * DKK + cc) = v;
            }
        }
    }
}

// =====================================================================
// Prep 3: K,V fp32 -> bf16 hi/lo; V transposed per hb.
// =====================================================================
__global__ __launch_bounds__(256) void cvt_kv_kernel() {
    const int kt = blockIdx.x;
    const int hb = blockIdx.y;
    const int tid = threadIdx.x;
    __shared__ float vs[64][33];

#pragma unroll
    for (int i = 0; i < 8; i++) {
        int idx = tid + i * 256;
        int key = idx >> 5;
        int dk  = idx & 31;
        size_t gsrc = ((size_t)hb * GGG + 1 + kt * 64 + key) * DKK + dk;
        float kv = g_K[gsrc];
        __nv_bfloat16 kh = __float2bfloat16(kv);
        size_t kd = ((size_t)hb * NKEY + kt * 64 + key) * DKK + dk;
        g_Kbh[kd] = kh;
        g_Kbl[kd] = __float2bfloat16(kv - __bfloat162float(kh));
        vs[key][dk] = g_V[gsrc];
    }
    __syncthreads();
#pragma unroll
    for (int i = 0; i < 8; i++) {
        int idx = tid + i * 256;
        int d = idx >> 6;
        int j = idx & 63;
        float vv = vs[j][d];
        __nv_bfloat16 vh = __float2bfloat16(vv);
        size_t o = ((size_t)hb * DKK + d) * NKEY + kt * 64 + j;
        g_Vtbh[o] = vh;
        g_Vtbl[o] = __float2bfloat16(vv - __bfloat162float(vh));
    }
}

// =====================================================================
// Kernel B (HMMA flash attention) — fixed-max softmax (M = MCONST),
// grid.x=4, cp.async 2-stage, hoisted Qm fragments. (256,2).
// =====================================================================
#define STQ 40
#define STK 40
#define STV 72
#define O_QMHI 0
#define O_QMLO 10240
#define O_EPHI 20480
#define O_EPLO 30720
#define O_EDHI 40960
#define O_EDLO 51200
#define O_KV   61440
#define KV_STAGE 19456
#define KV_KHI 0
#define KV_KLO 5120
#define KV_VHI 10240
#define KV_VLO 14848
#define SMEM_ATTN (O_KV + 2 * KV_STAGE)   // 100352

__device__ __forceinline__ void load_kv_tile(uint32_t sbase, int stage, int hb, int t, int tid) {
    const uint32_t dstS = sbase + O_KV + stage * KV_STAGE;
#pragma unroll
    for (int i = 0; i < 4; i++) {
        int c = tid + i * 256;
        if (c < 512) {
            int half = c >> 8;
            int cc = c & 255;
            int row = cc >> 2, qd = cc & 3;
            const __nv_bfloat16* src = (half ? g_Kbl : g_Kbh)
                + ((size_t)hb * NKEY + t * 64 + row) * DKK + qd * 8;
            uint32_t dst = dstS + (half ? KV_KLO : KV_KHI) + row * (STK * 2) + qd * 16;
            CP_ASYNC16(dst, src);
        } else {
            int half = (c >> 8) & 1;
            int cc = c & 255;
            int row = cc >> 3, qd = cc & 7;
            const __nv_bfloat16* src = (half ? g_Vtbl : g_Vtbh)
                + ((size_t)hb * DKK + row) * NKEY + t * 64 + qd * 8;
            uint32_t dst = dstS + (half ? KV_VLO : KV_VHI) + row * (STV * 2) + qd * 16;
            CP_ASYNC16(dst, src);
        }
    }
}

__global__ __launch_bounds__(256, 2) void attn_hmma_kernel() {
    extern __shared__ char sm[];
    const int qbase = blockIdx.x * 128;
    const int b     = blockIdx.y;
    const int head  = blockIdx.z;
    const int hb    = head * BBB + b;
    const int tid   = threadIdx.x;
    const int warp  = tid >> 5;
    const int lane  = tid & 31;
    const int g     = lane >> 2;
    const int tig   = lane & 3;

    const uint32_t sbase = smem_u32(sm);
    __nv_bfloat16* sQmHi = (__nv_bfloat16*)(sm + O_QMHI);
    __nv_bfloat16* sQmLo = (__nv_bfloat16*)(sm + O_QMLO);
    __nv_bfloat16* sEpHi = (__nv_bfloat16*)(sm + O_EPHI);
    __nv_bfloat16* sEpLo = (__nv_bfloat16*)(sm + O_EPLO);
    __nv_bfloat16* sEdHi = (__nv_bfloat16*)(sm + O_EDHI);
    __nv_bfloat16* sEdLo = (__nv_bfloat16*)(sm + O_EDLO);

    load_kv_tile(sbase, 0, hb, 0, tid);
    CP_COMMIT();

    // ---- prologue: convert queries into smem (scaled, hi/lo) ----
    for (int idx = tid; idx < 1024; idx += 256) {
        int row = idx >> 3, c4 = idx & 7;
        int qc = qbase + row;
        const int so = row * STQ + c4 * 4;
        {
            const float4 v = *(const float4*)(g_Q + ((size_t)hb * GGG + qc) * DKK + c4 * 4);
            uint32_t h0, l0, h1, l1;
            split2(v.x * NORMF, v.y * NORMF, h0, l0);
            split2(v.z * NORMF, v.w * NORMF, h1, l1);
            *(uint2*)(sQmHi + so) = make_uint2(h0, h1);
            *(uint2*)(sQmLo + so) = make_uint2(l0, l1);
        }
        if (qc == 0) {
            *(uint2*)(sEpHi + so) = make_uint2(0, 0);
            *(uint2*)(sEpLo + so) = make_uint2(0, 0);
            *(uint2*)(sEdHi + so) = make_uint2(0, 0);
            *(uint2*)(sEdLo + so) = make_uint2(0, 0);
        } else {
            bool pick = (qc <= NPP);
            int ppd = pick ? (qc - 1) : (qc - NPP - 1);
            size_t xo = ((size_t)hb * NPP + ppd) * DKK + c4 * 4;
            const float4 ve = *(const float4*)((pick ? g_Qx[1] : g_Qx[5]) + xo);
            const float4 vd = *(const float4*)((pick ? g_Qx[2] : g_Qx[4]) + xo);
            uint32_t h0, l0, h1, l1;
            split2(ve.x * NORMF, ve.y * NORMF, h0, l0);
            split2(ve.z * NORMF, ve.w * NORMF, h1, l1);
            *(uint2*)(sEpHi + so) = make_uint2(h0, h1);
            *(uint2*)(sEpLo + so) = make_uint2(l0, l1);
            split2(vd.x * NORMF, vd.y * NORMF, h0, l0);
            split2(vd.z * NORMF, vd.w * NORMF, h1, l1);
            *(uint2*)(sEdHi + so) = make_uint2(h0, h1);
            *(uint2*)(sEdLo + so) = make_uint2(l0, l1);
        }
    }

    // ---- init from key 0 (main query only), fixed shift ----
    const int r0g = qbase + warp * 16 + g;
    const int r1g = r0g + 8;
    float l0, l1;
    float acc[4][4];
    {
        const float* K0 = g_K + (size_t)hb * GGG * DKK;
        const float* V0 = g_V + (size_t)hb * GGG * DKK;
        const float* q0 = g_Q + ((size_t)hb * GGG + r0g) * DKK;
        const float* q1 = g_Q + ((size_t)hb * GGG + r1g) * DKK;
        float s0 = 0.f, s1 = 0.f;
#pragma unroll
        for (int k = 0; k < DKK; k++) {
            float kk = K0[k];
            s0 = fmaf(q0[k], kk, s0);
            s1 = fmaf(q1[k], kk, s1);
        }
        float w00 = __expf(s0 * NORMF - MCONST);
        float w01 = __expf(s1 * NORMF - MCONST);
        l0 = (tig == 0) ? w00 : 0.f;
        l1 = (tig == 0) ? w01 : 0.f;
#pragma unroll
        for (int vf = 0; vf < 4; vf++) {
            float va = V0[vf * 8 + 2 * tig];
            float vb = V0[vf * 8 + 2 * tig + 1];
            acc[vf][0] = w00 * va; acc[vf][1] = w00 * vb;
            acc[vf][2] = w01 * va; acc[vf][3] = w01 * vb;
        }
    }

    const int rowA  = warp * 16 + (lane & 7) + ((lane >> 3) & 1) * 8;
    const int colA0 = ((lane >> 4) & 1) * 8;
    const uint32_t aoff = (uint32_t)(rowA * STQ + colA0) * 2;
    const uint32_t aQmHi = sbase + O_QMHI + aoff;
    const uint32_t aQmLo = sbase + O_QMLO + aoff;
    const uint32_t aEpHi = sbase + O_EPHI + aoff;
    const uint32_t aEpLo = sbase + O_EPLO + aoff;
    const uint32_t aEdHi = sbase + O_EDHI + aoff;
    const uint32_t aEdLo = sbase + O_EDLO + aoff;
    const int rowB  = lane & 7;
    const int colB0 = ((lane >> 3) & 1) * 8;
    const uint32_t bKoff = (uint32_t)(rowB * STK + colB0) * 2;
    const uint32_t bVoff = (uint32_t)(rowB * STV + colB0) * 2;

    const bool extra0 = (r0g != 0);

    // ---- hoist Qm fragments (constant across all tiles) ----
    __syncthreads();
    uint32_t fQmHi[2][4], fQmLo[2][4];
    LDMX4(fQmHi[0], aQmHi);
    LDMX4(fQmHi[1], aQmHi + 32);
    LDMX4(fQmLo[0], aQmLo);
    LDMX4(fQmLo[1], aQmLo + 32);

#pragma unroll 1
    for (int t = 0; t < 8; t++) {
        CP_WAIT0();
        __syncthreads();
        if (t < 7) {
            load_kv_tile(sbase, (t + 1) & 1, hb, t + 1, tid);
            CP_COMMIT();
        }

        const uint32_t stK = sbase + O_KV + (t & 1) * KV_STAGE;
        const uint32_t aEHi = (t < 4) ? aEpHi : aEdHi;
        const uint32_t aELo = (t < 4) ? aEpLo : aEdLo;

#pragma unroll
        for (int half = 0; half < 2; half++) {
            float S1[4][4], S2[4][4];
#pragma unroll
            for (int nf = 0; nf < 4; nf++)
#pragma unroll
                for (int j = 0; j < 4; j++) { S1[nf][j] = 0.f; S2[nf][j] = 0.f; }

#pragma unroll
            for (int ks = 0; ks < 2; ks++) {
                uint32_t ae[4], af[4];
                LDMX4(ae, aEHi + ks * 32);
                LDMX4(af, aELo + ks * 32);
#pragma unroll
                for (int nf = 0; nf < 4; nf++) {
                    uint32_t kaddr = stK + bKoff + (uint32_t)((half * 4 + nf) * 8) * (STK * 2) + ks * 32;
                    uint32_t kh[2], kl[2];
                    LDMX2(kh, kaddr + KV_KHI);
                    LDMX2(kl, kaddr + KV_KLO);
                    MMA16816(S1[nf], fQmHi[ks], kh[0], kh[1]);
                    MMA16816(S1[nf], fQmLo[ks], kh[0], kh[1]);
                    MMA16816(S1[nf], fQmHi[ks], kl[0], kl[1]);
                    MMA16816(S2[nf], ae, kh[0], kh[1]);
                    MMA16816(S2[nf], af, kh[0], kh[1]);
                    MMA16816(S2[nf], ae, kl[0], kl[1]);
                }
            }

            // ---- fixed-shift weights (no max tracking, no rescale) ----
#pragma unroll
            for (int nf = 0; nf < 4; nf++) {
                float w0 = __expf(S1[nf][0] - MCONST);
                float w1 = __expf(S1[nf][1] - MCONST);
                float w2 = __expf(S1[nf][2] - MCONST);
                float w3 = __expf(S1[nf][3] - MCONST);
                if (extra0) {
                    w0 += __expf(S2[nf][0] - MCONST);
                    w1 += __expf(S2[nf][1] - MCONST);
                }
                w2 += __expf(S2[nf][2] - MCONST);
                w3 += __expf(S2[nf][3] - MCONST);
                l0 += w0 + w1; l1 += w2 + w3;
                S1[nf][0] = w0; S1[nf][1] = w1; S1[nf][2] = w2; S1[nf][3] = w3;
            }

            // ---- P @ V ----
#pragma unroll
            for (int ks2 = 0; ks2 < 2; ks2++) {
                uint32_t ph[4], pl[4];
                split2(S1[2 * ks2][0], S1[2 * ks2][1], ph[0], pl[0]);
                split2(S1[2 * ks2][2], S1[2 * ks2][3], ph[1], pl[1]);
                split2(S1[2 * ks2 + 1][0], S1[2 * ks2 + 1][1], ph[2], pl[2]);
                split2(S1[2 * ks2 + 1][2], S1[2 * ks2 + 1][3], ph[3], pl[3]);
#pragma unroll
                for (int vf = 0; vf < 4; vf++) {
                    uint32_t vaddr = stK + bVoff + (uint32_t)(vf * 8) * (STV * 2)
                                   + (half * 2 + ks2) * 32;
                    uint32_t vh[2], vl[2];
                    LDMX2(vh, vaddr + KV_VHI);
                    LDMX2(vl, vaddr + KV_VLO);
                    MMA16816(acc[vf], ph, vh[0], vh[1]);
                    MMA16816(acc[vf], pl, vh[0], vh[1]);
                    MMA16816(acc[vf], ph, vl[0], vl[1]);
                }
            }
        }
    }

    // ---- diagonal extra logit (single key per row), fixed shift ----
#pragma unroll
    for (int r = 0; r < 2; r++) {
        int qq = (r == 0) ? r0g : r1g;
        if (qq >= 1) {
            bool pick = (qq <= NPP);
            int nd = pick ? (NPP + qq) : (qq - NPP);
            int ppd = pick ? (qq - 1) : (qq - NPP - 1);
            const float* qg = (pick ? g_Qx[0] : g_Qx[3]) + ((size_t)hb * NPP + ppd) * DKK;
            const float* kk = g_K + ((size_t)hb * GGG + nd) * DKK;
            const float* vv = g_V + ((size_t)hb * GGG + nd) * DKK;
            float s = 0.f;
#pragma unroll
            for (int k = 0; k < DKK; k++) s = fmaf(qg[k], kk[k], s);
            float w = __expf(s * NORMF - MCONST);
            float& l = (r == 0) ? l0 : l1;
            if (tig == 0) l += w;
#pragma unroll
            for (int vf = 0; vf < 4; vf++) {
                acc[vf][2 * r]     = fmaf(w, vv[vf * 8 + 2 * tig], acc[vf][2 * r]);
                acc[vf][2 * r + 1] = fmaf(w, vv[vf * 8 + 2 * tig + 1], acc[vf][2 * r + 1]);
            }
        }
    }

    // ---- finalize: write heads as bf16 hi/lo ----
    l0 += __shfl_xor_sync(0xffffffffu, l0, 1);
    l0 += __shfl_xor_sync(0xffffffffu, l0, 2);
    l1 += __shfl_xor_sync(0xffffffffu, l1, 1);
    l1 += __shfl_xor_sync(0xffffffffu, l1, 2);
    float inv0 = 1.f / l0, inv1 = 1.f / l1;

    {
        size_t base = ((size_t)(b * GGG + r0g) * HH + head) * DKK;
#pragma unroll
        for (int vf = 0; vf < 4; vf++) {
            uint32_t hi, lo;
            split2(acc[vf][0] * inv0, acc[vf][1] * inv0, hi, lo);
            *(uint32_t*)(g_headshi + base + vf * 8 + 2 * tig) = hi;
            *(uint32_t*)(g_headslo + base + vf * 8 + 2 * tig) = lo;
        }
    }
    {
        size_t base = ((size_t)(b * GGG + r1g) * HH + head) * DKK;
#pragma unroll
        for (int vf = 0; vf < 4; vf++) {
            uint32_t hi, lo;
            split2(acc[vf][2] * inv1, acc[vf][3] * inv1, hi, lo);
            *(uint32_t*)(g_headshi + base + vf * 8 + 2 * tig) = hi;
            *(uint32_t*)(g_headslo + base + vf * 8 + 2 * tig) = lo;
        }
    }
}

// =====================================================================
// Kernel B2: scalar tail for q = 512 (one block per hb, 256 threads).
// =====================================================================
__global__ __launch_bounds__(256) void attn_tail_kernel() {
    const int hb   = blockIdx.x;
    const int head = hb / BBB;
    const int b    = hb - head * BBB;
    const int tid  = threadIdx.x;
    const int q    = GGG - 1;
    const int pd   = q - NPP - 1;

    __shared__ float qm[DKK], qp[DKK], qd[DKK], qg[DKK];
    __shared__ float s1[GGG], s2[GGG];
    __shared__ float red[256];
    __shared__ float pacc[8][DKK];
    __shared__ float s_m, s_l, s_sd;

    const float* Kb = g_K + (size_t)hb * GGG * DKK;
    const float* Vb = g_V + (size_t)hb * GGG * DKK;
    const size_t xoff = ((size_t)hb * NPP + pd) * DKK;

    if (tid < DKK)          qm[tid]        = NORMF * g_Q[((size_t)hb * GGG + q) * DKK + tid];
    else if (tid < 2 * DKK) qp[tid - 32]   = NORMF * g_Qx[5][xoff + tid - 32];
    else if (tid < 3 * DKK) qd[tid - 64]   = NORMF * g_Qx[4][xoff + tid - 64];
    else if (tid < 4 * DKK) qg[tid - 96]   = g_Qx[3][xoff + tid - 96];
    __syncthreads();

    for (int n = tid; n < GGG; n += 256) {
        const float* kk = Kb + (size_t)n * DKK;
        float a = 0.f, e = 0.f;
        const float* qe = (n <= NPP) ? qp : qd;
#pragma unroll
        for (int k = 0; k < DKK; k++) {
            a = fmaf(qm[k], kk[k], a);
            e = fmaf(qe[k], kk[k], e);
        }
        s1[n] = a;
        s2[n] = (n >= 1) ? e : -3.0e38f;
    }
    if (tid == 0) {
        const float* kk = Kb + (size_t)(1 + pd) * DKK;
        float s = 0.f;
#pragma unroll
        for (int k = 0; k < DKK; k++) s = fmaf(qg[k], kk[k], s);
        s_sd = s * NORMF;
    }
    __syncthreads();

    float mx = -3.0e38f;
    for (int n = tid; n < GGG; n += 256) mx = fmaxf(mx, fmaxf(s1[n], s2[n]));
    if (tid == 0) mx = fmaxf(mx, s_sd);
    red[tid] = mx;
    __syncthreads();
    for (int s = 128; s > 0; s >>= 1) {
        if (tid < s) red[tid] = fmaxf(red[tid], red[tid + s]);
        __syncthreads();
    }
    if (tid == 0) s_m = red[0];
    __syncthreads();
    const float m = s_m;

    float ls = 0.f;
    for (int n = tid; n < GGG; n += 256) {
        float w = __expf(s1[n] - m);
        if (n >= 1) w += __expf(s2[n] - m);
        if (n == 1 + pd) w += __expf(s_sd - m);
        s1[n] = w;
        ls += w;
    }
    red[tid] = ls;
    __syncthreads();
    for (int s = 128; s > 0; s >>= 1) {
        if (tid < s) red[tid] += red[tid + s];
        __syncthreads();
    }
    if (tid == 0) s_l = red[0];
    __syncthreads();

    const int dk  = tid & 31;
    const int grp = tid >> 5;
    float a = 0.f;
    for (int n = grp; n < GGG; n += 8)
        a = fmaf(s1[n], Vb[(size_t)n * DKK + dk], a);
    pacc[grp][dk] = a;
    __syncthreads();

    if (tid < DKK) {
        float v = 0.f;
#pragma unroll
        for (int gg = 0; gg < 8; gg++) v += pacc[gg][tid];
        v /= s_l;
        __nv_bfloat16 hi = __float2bfloat16(v);
        size_t base = ((size_t)(b * GGG + q) * HH + head) * DKK + tid;
        g_headshi[base] = hi;
        g_headslo[base] = __float2bfloat16(v - __bfloat162float(hi));
    }
}

// =====================================================================
// Kernel C (HMMA): out = heads(8208x256) @ WoutT^T.  (256,2).
// =====================================================================
#define XS_STRIDE 72

__global__ __launch_bounds__(256, 2) void out_hmma_kernel(float* __restrict__ out) {
    const int M = BBB * GGG;
    const int row0 = blockIdx.x * 128;
    const int col0 = blockIdx.y * 32;
    if (row0 >= M) return;

    __shared__ __nv_bfloat16 Xs[2][128][XS_STRIDE];
    __shared__ __nv_bfloat16 Ws[2][32][XS_STRIDE];

    const int tid  = threadIdx.x;
    const int warp = tid >> 5;
    const int lane = tid & 31;
    const int g    = lane >> 2;
    const int tig  = lane & 3;

    float acc[4][4];
#pragma unroll
    for (int nf = 0; nf < 4; nf++)
#pragma unroll
        for (int i = 0; i < 4; i++) acc[nf][i] = 0.f;

    const int rowA  = warp * 16 + (lane & 7) + ((lane >> 3) & 1) * 8;
    const int colA0 = ((lane >> 4) & 1) * 8;
    const uint32_t addrAhi0 = smem_u32(&Xs[0][rowA][colA0]);
    const uint32_t addrAlo0 = smem_u32(&Xs[1][rowA][colA0]);
    const int rowB  = lane & 7;
    const int colB0 = ((lane >> 3) & 1) * 8;
    const int nfsel = (lane >> 4) & 1;
    uint32_t addrBhiP[2], addrBloP[2];
#pragma unroll
    for (int p = 0; p < 2; p++) {
        addrBhiP[p] = smem_u32(&Ws[0][(2 * p + nfsel) * 8 + rowB][colB0]);
        addrBloP[p] = smem_u32(&Ws[1][(2 * p + nfsel) * 8 + rowB][colB0]);
    }

#pragma unroll 1
    for (int c = 0; c < 4; c++) {
        const int dc = c * 64;
        __syncthreads();
#pragma unroll
        for (int i = 0; i < 4; i++) {
            int idx = tid + i * 256;
            int row = idx >> 3;
            int v   = idx & 7;
            int gr  = row0 + row;
            int grc = (gr < M) ? gr : (M - 1);
            size_t gix = (size_t)grc * 256 + dc + v * 8;
            *(uint4*)&Xs[0][row][v * 8] = *(const uint4*)(g_headshi + gix);
            *(uint4*)&Xs[1][row][v * 8] = *(const uint4*)(g_headslo + gix);
        }
        {
            int row = tid >> 3;
            int v   = tid & 7;
            size_t gix = (size_t)(col0 + row) * 256 + dc + v * 8;
            *(uint4*)&Ws[0][row][v * 8] = *(const uint4*)(g_WoThi + gix);
            *(uint4*)&Ws[1][row][v * 8] = *(const uint4*)(g_WoTlo + gix);
        }
        __syncthreads();

#pragma unroll
        for (int ks = 0; ks < 4; ks++) {
            const uint32_t kadd = ks * 32;
            uint32_t ahi[4], alo[4];
            LDMX4(ahi, addrAhi0 + kadd);
            LDMX4(alo, addrAlo0 + kadd);
#pragma unroll
            for (int p = 0; p < 2; p++) {
                uint32_t bh[4], bl[4];
                LDMX4(bh, addrBhiP[p] + kadd);
                LDMX4(bl, addrBloP[p] + kadd);
                MMA16816(acc[2 * p],     ahi, bh[0], bh[1]);
                MMA16816(acc[2 * p],     alo, bh[0], bh[1]);
                MMA16816(acc[2 * p],     ahi, bl[0], bl[1]);
                MMA16816(acc[2 * p + 1], ahi, bh[2], bh[3]);
                MMA16816(acc[2 * p + 1], alo, bh[2], bh[3]);
                MMA16816(acc[2 * p + 1], ahi, bl[2], bl[3]);
            }
        }
    }

    const int r0 = row0 + warp * 16 + g;
    const int r1 = r0 + 8;
#pragma unroll
    for (int nf = 0; nf < 4; nf++) {
        const int col = col0 + nf * 8 + tig * 2;
        if (r0 < M) {
            float2 v = make_float2(acc[nf][0], acc[nf][1]);
            *(float2*)(out + (size_t)r0 * EE + col) = v;
        }
        if (r1 < M) {
            float2 v = make_float2(acc[nf][2], acc[nf][3]);
            *(float2*)(out + (size_t)r1 * EE + col) = v;
        }
    }
}

// =====================================================================
extern "C" void kernel_launch(void* const* d_in, const int* in_sizes, int n_in,
                              void* d_out, int out_size) {
    const float* q = (const float*)d_in[0];
    const float* h = (const float*)d_in[1];
    WPtrs WP;
    for (int i = 0; i < 9; i++) WP.w[i] = (const float*)d_in[2 + i];
    const float* Wout = (const float*)d_in[11];
    float* out = (float*)d_out;

    cudaFuncSetAttribute(attn_hmma_kernel, cudaFuncAttributeMaxDynamicSharedMemorySize, SMEM_ATTN);
    cudaFuncSetAttribute(proj_hmma_kernel, cudaFuncAttributeMaxDynamicSharedMemorySize, PROJ_SMEM);

    cvt_all_kernel<<<2 * NB_X + NB_W + NB_WO, 256>>>(q, h, WP, Wout);

    proj_hmma_kernel<<<dim3(65, 2, 9), 256, PROJ_SMEM>>>();

    cvt_kv_kernel<<<dim3(8, HH * BBB), 256>>>();

    attn_hmma_kernel<<<dim3(4, BBB, HH), 256, SMEM_ATTN>>>();
    attn_tail_kernel<<<HH * BBB, 256>>>();

    out_hmma_kernel<<<dim3((BBB * GGG + 127) / 128, EE / 32), 256>>>(out);
}